// round 12
// baseline (speedup 1.0000x reference)
#include <cuda_runtime.h>
#include <cuda_bf16.h>
#include <cuda_fp16.h>
#include <cstdint>

#define BB 2
#define LL 1024
#define DIN 768
#define DM 1536
#define DS 16
#define DD 96
#define NL 4
#define ROWS (BB*LL)   // 2048
#define VOCAB 32000
#define KW_IN (DIN/2)  // 384
#define KW_DM (DM/2)   // 768
#define KW_DD (DD/2)   // 48

// ---------------- scratch (static device globals; no allocation) ----------------
__device__ float g_seq[ROWS*DIN];
__device__ float g_ab [ROWS*2*DM];
__device__ float g_ac [ROWS*DM];
__device__ float g_Bm [ROWS*DS];
__device__ float g_Cm [ROWS*DS];
__device__ float g_delta[ROWS*DM];
__device__ float g_wpack[NL*128*DM];

// packed fp16x2 activations (single array each — weights carry the split)
__device__ unsigned g_xn_fp[ROWS*KW_IN];
__device__ unsigned g_so_fp[ROWS*KW_DM];
__device__ unsigned g_dt_fp[ROWS*KW_DD];
// weights: exact fp16 hi/lo split (hi+lo == fp32 weight to ~22 bits)
__device__ unsigned g_wi_hi[NL*2*DM*KW_IN], g_wi_lo[NL*2*DM*KW_IN];
__device__ unsigned g_wo_hi[NL*DIN*KW_DM],  g_wo_lo[NL*DIN*KW_DM];
__device__ unsigned g_d1_hi[NL*DM*KW_DD],   g_d1_lo[NL*DM*KW_DD];
// head weights single fp16 (1-pass head)
__device__ unsigned g_wh_fp[VOCAB*KW_IN];

__device__ __forceinline__ float siluf(float x){ return x / (1.f + __expf(-x)); }
__device__ __forceinline__ float softplusf(float x){ return fmaxf(x,0.f) + log1pf(expf(-fabsf(x))); }

__device__ __forceinline__ unsigned pack_fp16(float x0, float x1){
    __half h0 = __float2half_rn(x0);
    __half h1 = __float2half_rn(x1);
    return ((unsigned)__half_as_ushort(h1) << 16) | __half_as_ushort(h0);
}
__device__ __forceinline__ unsigned pack_fp16_split(float x0, float x1, unsigned &lopair){
    __half h0 = __float2half_rn(x0);
    __half h1 = __float2half_rn(x1);
    __half l0 = __float2half_rn(x0 - __half2float(h0));
    __half l1 = __float2half_rn(x1 - __half2float(h1));
    lopair = ((unsigned)__half_as_ushort(l1) << 16) | __half_as_ushort(l0);
    return ((unsigned)__half_as_ushort(h1) << 16) | __half_as_ushort(h0);
}

__device__ __forceinline__ void mma_fp16(float* d, const unsigned* a, const unsigned* b){
    asm volatile(
      "mma.sync.aligned.m16n8k16.row.col.f32.f16.f16.f32 "
      "{%0,%1,%2,%3}, {%4,%5,%6,%7}, {%8,%9}, {%0,%1,%2,%3};\n"
      : "+f"(d[0]),"+f"(d[1]),"+f"(d[2]),"+f"(d[3])
      : "r"(a[0]),"r"(a[1]),"r"(a[2]),"r"(a[3]), "r"(b[0]),"r"(b[1]));
}
__device__ __forceinline__ void cp16(void* s, const void* g){
    unsigned a = (unsigned)__cvta_generic_to_shared(s);
    asm volatile("cp.async.cg.shared.global [%0], [%1], 16;" :: "r"(a), "l"(g));
}

// ---------------- weight split: fp32 [Nrows,K] -> packed fp16x2 hi/lo (exact) --------
__global__ void split16_kernel(const float* __restrict__ src, unsigned* __restrict__ hi,
                               unsigned* __restrict__ lo, int totalWords, int K){
    int idx = blockIdx.x*256 + threadIdx.x;
    if (idx >= totalWords) return;
    int Kw = K >> 1;
    int n = idx / Kw, w = idx - n*Kw;
    int k = 2*w;
    unsigned l; unsigned h = pack_fp16_split(src[(size_t)n*K + k], src[(size_t)n*K + k + 1], l);
    hi[idx] = h; lo[idx] = l;
}

// ---------------- fp16 pack: fp32 [Nrows,K] -> packed fp16x2 ----------------
__global__ void fp16_pack_kernel(const float* __restrict__ src, unsigned* __restrict__ dst,
                                 int totalWords, int K){
    int idx = blockIdx.x*256 + threadIdx.x;
    if (idx >= totalWords) return;
    int Kw = K >> 1;
    int n = idx / Kw, w = idx - n*Kw;
    int k = 2*w;
    dst[idx] = pack_fp16(src[(size_t)n*K + k], src[(size_t)n*K + k + 1]);
}

// ---------------- embedding gather ----------------
__global__ void embed_kernel(const int* __restrict__ tok, const float* __restrict__ emb){
    int row = blockIdx.x;
    int t = tok[row];
    for (int c = threadIdx.x; c < DIN; c += blockDim.x)
        g_seq[row*DIN + c] = emb[t*DIN + c];
}

// ---------------- rmsnorm -> packed fp16 output ----------------
__global__ void rmsnorm_kernel(const float* __restrict__ in, const float* __restrict__ w,
                               unsigned* __restrict__ fp){
    int row = blockIdx.x;
    float ss = 0.f;
    #pragma unroll
    for (int i = 0; i < 3; i++){
        float x = in[row*DIN + threadIdx.x + i*256];
        ss += x*x;
    }
    #pragma unroll
    for (int off = 16; off > 0; off >>= 1) ss += __shfl_xor_sync(0xffffffffu, ss, off);
    __shared__ float red[8];
    if ((threadIdx.x & 31) == 0) red[threadIdx.x >> 5] = ss;
    __syncthreads();
    float ms = 0.f;
    #pragma unroll
    for (int i = 0; i < 8; i++) ms += red[i];
    float r = rsqrtf(ms * (1.f/768.f) + 1e-6f);
    for (int p = threadIdx.x; p < KW_IN; p += 256){
        int c = 2*p;
        float y0 = in[row*DIN + c]     * r * w[c];
        float y1 = in[row*DIN + c + 1] * r * w[c+1];
        fp[row*KW_IN + p] = pack_fp16(y0, y1);
    }
}

// ========== 2-pass fp16 GEMM with exact split weights ==========
// C[M,N] = A[M,K] @ (Bh+Bl)[N,K]^T ; error = fp16 rounding of A only.
// 256 thr, 8 warps (4Mx2N), warp 32x64, BK=16, cp.async double buffer.
__global__ void __launch_bounds__(256,2) gemm_f16x2_kernel(
    const unsigned* __restrict__ A,
    const unsigned* __restrict__ Bhi, const unsigned* __restrict__ Blo,
    float* __restrict__ C, int M, int N, int K,
    const float* __restrict__ bias, const float* __restrict__ resid, int act)
{
    __shared__ unsigned sm[2][3][128*8];   // [stage][A,Bhi,Blo][row*8+w]
    int tid = threadIdx.x;
    int lane = tid & 31, warp = tid >> 5;
    int qr = lane >> 2, q = lane & 3;
    int m0 = (warp >> 1) * 32, n0 = (warp & 1) * 64;
    int brow = blockIdx.x * 128, bcol = blockIdx.y * 128;
    int Kw = K >> 1;
    int lrow = tid >> 1, lh = (tid & 1) << 2;
    int sidx = lrow*8 + lh;

    const unsigned* gA  = A   + (size_t)(brow + lrow)*Kw + lh;
    const unsigned* gBh = Bhi + (size_t)(bcol + lrow)*Kw + lh;
    const unsigned* gBl = Blo + (size_t)(bcol + lrow)*Kw + lh;

    float acc[2][8][4];
    #pragma unroll
    for (int im = 0; im < 2; im++)
        #pragma unroll
        for (int jn = 0; jn < 8; jn++)
            #pragma unroll
            for (int e = 0; e < 4; e++) acc[im][jn][e] = 0.f;

    int kt = K >> 4;

    cp16(&sm[0][0][sidx], gA);
    cp16(&sm[0][1][sidx], gBh);
    cp16(&sm[0][2][sidx], gBl);
    asm volatile("cp.async.commit_group;");

    for (int k = 0; k < kt; k++){
        int st = k & 1;
        if (k + 1 < kt){
            int s2 = (k+1) & 1;
            size_t off = (size_t)(k+1) * 8;
            cp16(&sm[s2][0][sidx], gA  + off);
            cp16(&sm[s2][1][sidx], gBh + off);
            cp16(&sm[s2][2][sidx], gBl + off);
            asm volatile("cp.async.commit_group;");
            asm volatile("cp.async.wait_group 1;");
        } else {
            asm volatile("cp.async.wait_group 0;");
        }
        __syncthreads();

        unsigned a[2][4];
        #pragma unroll
        for (int im = 0; im < 2; im++){
            int r0 = (m0 + im*16 + qr    )*8 + 2*q;
            int r1 = (m0 + im*16 + qr + 8)*8 + 2*q;
            uint2 h0 = *(const uint2*)&sm[st][0][r0];
            uint2 h1 = *(const uint2*)&sm[st][0][r1];
            a[im][0] = h0.x; a[im][1] = h1.x; a[im][2] = h0.y; a[im][3] = h1.y;
        }
        #pragma unroll
        for (int jn = 0; jn < 8; jn++){
            int rb = (n0 + jn*8 + qr)*8 + 2*q;
            uint2 bh2 = *(const uint2*)&sm[st][1][rb];
            uint2 bl2 = *(const uint2*)&sm[st][2][rb];
            unsigned bh[2] = {bh2.x, bh2.y};
            unsigned bl[2] = {bl2.x, bl2.y};
            #pragma unroll
            for (int im = 0; im < 2; im++) mma_fp16(acc[im][jn], a[im], bh);
            #pragma unroll
            for (int im = 0; im < 2; im++) mma_fp16(acc[im][jn], a[im], bl);
        }
        __syncthreads();
    }

    #pragma unroll
    for (int im = 0; im < 2; im++){
        #pragma unroll
        for (int h = 0; h < 2; h++){
            int m = brow + m0 + im*16 + qr + h*8;
            #pragma unroll
            for (int jn = 0; jn < 8; jn++){
                int n = bcol + n0 + jn*8 + 2*q;
                float v0 = acc[im][jn][h*2 + 0];
                float v1 = acc[im][jn][h*2 + 1];
                if (bias){ v0 += bias[n]; v1 += bias[n+1]; }
                if (act){ v0 = softplusf(v0); v1 = softplusf(v1); }
                if (resid){ v0 += resid[(size_t)m*N + n]; v1 += resid[(size_t)m*N + n + 1]; }
                *(float2*)&C[(size_t)m*N + n] = make_float2(v0, v1);
            }
        }
    }
}

// ========== single-pass fp16 GEMM (head), proven R7 structure ==========
__global__ void __launch_bounds__(256,2) gemm_fp16_kernel(
    const unsigned* __restrict__ A, const unsigned* __restrict__ B,
    float* __restrict__ C, int M, int N, int K)
{
    __shared__ unsigned sm[2][2][128*8];
    int tid = threadIdx.x;
    int lane = tid & 31, warp = tid >> 5;
    int qr = lane >> 2, q = lane & 3;
    int m0 = (warp >> 1) * 32, n0 = (warp & 1) * 64;
    int brow = blockIdx.x * 128, bcol = blockIdx.y * 128;
    int Kw = K >> 1;
    int lrow = tid >> 1, lh = (tid & 1) << 2;
    int sidx = lrow*8 + lh;

    const unsigned* gA = A + (size_t)(brow + lrow)*Kw + lh;
    const unsigned* gB = B + (size_t)(bcol + lrow)*Kw + lh;

    float acc[2][8][4];
    #pragma unroll
    for (int im = 0; im < 2; im++)
        #pragma unroll
        for (int jn = 0; jn < 8; jn++)
            #pragma unroll
            for (int e = 0; e < 4; e++) acc[im][jn][e] = 0.f;

    int kt = K >> 4;

    cp16(&sm[0][0][sidx], gA);
    cp16(&sm[0][1][sidx], gB);
    asm volatile("cp.async.commit_group;");

    for (int k = 0; k < kt; k++){
        int st = k & 1;
        if (k + 1 < kt){
            int s2 = (k+1) & 1;
            size_t off = (size_t)(k+1) * 8;
            cp16(&sm[s2][0][sidx], gA + off);
            cp16(&sm[s2][1][sidx], gB + off);
            asm volatile("cp.async.commit_group;");
            asm volatile("cp.async.wait_group 1;");
        } else {
            asm volatile("cp.async.wait_group 0;");
        }
        __syncthreads();

        unsigned a[2][4];
        #pragma unroll
        for (int im = 0; im < 2; im++){
            int r0 = (m0 + im*16 + qr    )*8 + 2*q;
            int r1 = (m0 + im*16 + qr + 8)*8 + 2*q;
            uint2 h0 = *(const uint2*)&sm[st][0][r0];
            uint2 h1 = *(const uint2*)&sm[st][0][r1];
            a[im][0] = h0.x; a[im][1] = h1.x; a[im][2] = h0.y; a[im][3] = h1.y;
        }
        #pragma unroll
        for (int jn = 0; jn < 8; jn++){
            int rb = (n0 + jn*8 + qr)*8 + 2*q;
            uint2 bb = *(const uint2*)&sm[st][1][rb];
            unsigned b[2] = {bb.x, bb.y};
            #pragma unroll
            for (int im = 0; im < 2; im++) mma_fp16(acc[im][jn], a[im], b);
        }
        __syncthreads();
    }

    #pragma unroll
    for (int im = 0; im < 2; im++){
        #pragma unroll
        for (int h = 0; h < 2; h++){
            int m = brow + m0 + im*16 + qr + h*8;
            #pragma unroll
            for (int jn = 0; jn < 8; jn++){
                int n = bcol + n0 + jn*8 + 2*q;
                *(float2*)&C[(size_t)m*N + n] =
                    make_float2(acc[im][jn][h*2 + 0], acc[im][jn][h*2 + 1]);
            }
        }
    }
}

// ---------------- causal depthwise conv (K=4) + SiLU ----------------
__global__ void conv_silu_kernel(const float* __restrict__ cw, const float* __restrict__ cb){
    int d = blockIdx.x * blockDim.x + threadIdx.x;
    int row = blockIdx.y;
    int t = row & (LL-1);
    float4 w = *(const float4*)(cw + d*4);
    float acc = cb[d];
    const float* p = g_ab + (size_t)row*(2*DM) + d;
    if (t >= 3) acc += p[-3*2*DM]*w.x;
    if (t >= 2) acc += p[-2*2*DM]*w.y;
    if (t >= 1) acc += p[-1*2*DM]*w.z;
    acc += p[0]*w.w;
    g_ac[(size_t)row*DM + d] = siluf(acc);
}

// ---------------- pack sB|sC|sD0 into one [NL][128][DM] weight ----------------
__global__ void pack_kernel(const float* __restrict__ sB, const float* __restrict__ sC,
                            const float* __restrict__ sD0){
    int idx = blockIdx.x*256 + threadIdx.x;
    if (idx >= NL*128*DM) return;
    int k = idx % DM;
    int n = (idx / DM) & 127;
    int l = idx / (128*DM);
    float v;
    if (n < 16)      v = sB [((size_t)l*DS + n     )*DM + k];
    else if (n < 32) v = sC [((size_t)l*DS + (n-16))*DM + k];
    else             v = sD0[((size_t)l*DD + (n-32))*DM + k];
    g_wpack[idx] = v;
}

// ---------------- fused small projections: [16 rows] x [128 outs], K=1536 ----------------
// outputs: B, C fp32; dt packed fp16
#define SP_KC 64
__global__ void __launch_bounds__(256) small_proj_kernel(const float* __restrict__ wp){
    __shared__ float Ws[128][SP_KC+1];
    __shared__ float Xs[16][SP_KC+4];
    int m0  = blockIdx.x * 16;
    int tid = threadIdx.x;
    int n2  = tid & 63;
    int mh  = tid >> 6;
    float acc[2][4] = {{0.f,0.f,0.f,0.f},{0.f,0.f,0.f,0.f}};

    for (int k0 = 0; k0 < DM; k0 += SP_KC){
        #pragma unroll
        for (int j = 0; j < 8; j++){
            int idx = tid + j*256;
            int r = idx >> 4, c4 = (idx & 15) << 2;
            float4 v = *(const float4*)(wp + (size_t)r*DM + k0 + c4);
            Ws[r][c4+0]=v.x; Ws[r][c4+1]=v.y; Ws[r][c4+2]=v.z; Ws[r][c4+3]=v.w;
        }
        {
            int r = tid >> 4, c4 = (tid & 15) << 2;
            float4 v = *(const float4*)(g_ac + (size_t)(m0+r)*DM + k0 + c4);
            Xs[r][c4+0]=v.x; Xs[r][c4+1]=v.y; Xs[r][c4+2]=v.z; Xs[r][c4+3]=v.w;
        }
        __syncthreads();
        #pragma unroll 8
        for (int kk = 0; kk < SP_KC; kk++){
            float w0 = Ws[2*n2][kk], w1 = Ws[2*n2+1][kk];
            #pragma unroll
            for (int i = 0; i < 4; i++){
                float x = Xs[mh*4+i][kk];
                acc[0][i] += w0*x;
                acc[1][i] += w1*x;
            }
        }
        __syncthreads();
    }
    #pragma unroll
    for (int i = 0; i < 4; i++){
        int m = m0 + mh*4 + i;
        int n = 2*n2;
        if (n2 < 8){
            g_Bm[m*DS + n]   = acc[0][i];
            g_Bm[m*DS + n+1] = acc[1][i];
        } else if (n2 < 16){
            g_Cm[m*DS + (n-16)]   = acc[0][i];
            g_Cm[m*DS + (n-16)+1] = acc[1][i];
        } else {
            g_dt_fp[m*KW_DD + (n2-16)] = pack_fp16(acc[0][i], acc[1][i]);
        }
    }
}

// ---------------- selective scan, prefetch ring depth 8; fp16 packed out -----------
#define PD 8
__global__ void scan_kernel(const float* __restrict__ A_log, const float* __restrict__ Dp){
    int lane = threadIdx.x & 31, warp = threadIdx.x >> 5;
    int s = lane & 15;
    int d = blockIdx.x*8 + warp*2 + (lane >> 4);
    int b = blockIdx.y;
    float Acoef = -expf(A_log[d*DS + s]);
    float Dv = Dp[d];
    const float* pd = g_delta + (size_t)(b*LL)*DM + d;
    const float* pa = g_ac    + (size_t)(b*LL)*DM + d;
    const float* pg = g_ab    + (size_t)(b*LL)*(2*DM) + DM + d;
    const float* pB = g_Bm    + (size_t)(b*LL)*DS + s;
    const float* pC = g_Cm    + (size_t)(b*LL)*DS + s;
    float f_d[PD], f_a[PD], f_g[PD], f_B[PD], f_C[PD];
    #pragma unroll
    for (int i = 0; i < PD; i++){
        f_d[i] = pd[(size_t)i*DM];
        f_a[i] = pa[(size_t)i*DM];
        f_g[i] = pg[(size_t)i*2*DM];
        f_B[i] = pB[(size_t)i*DS];
        f_C[i] = pC[(size_t)i*DS];
    }
    float h = 0.f;
    int p = blockIdx.x*4 + warp;        // d-pair index within KW_DM
    int wbase = (b*LL)*KW_DM + p;
    #pragma unroll 8
    for (int t = 0; t < LL; t++){
        int sl = t & (PD-1);
        float dc = f_d[sl], a_c = f_a[sl], gc = f_g[sl];
        float bc = f_B[sl], cc = f_C[sl];
        int tn = t + PD;
        if (tn < LL){
            f_d[sl] = pd[(size_t)tn*DM];
            f_a[sl] = pa[(size_t)tn*DM];
            f_g[sl] = pg[(size_t)tn*2*DM];
            f_B[sl] = pB[(size_t)tn*DS];
            f_C[sl] = pC[(size_t)tn*DS];
        }
        h = __expf(dc*Acoef)*h + dc*bc*a_c;
        float c = h*cc;
        c += __shfl_xor_sync(0xffffffffu, c, 8);
        c += __shfl_xor_sync(0xffffffffu, c, 4);
        c += __shfl_xor_sync(0xffffffffu, c, 2);
        c += __shfl_xor_sync(0xffffffffu, c, 1);
        float o = (c + Dv*a_c) * siluf(gc);
        float o2 = __shfl_xor_sync(0xffffffffu, o, 16);
        if (lane == 0)
            g_so_fp[wbase + t*KW_DM] = pack_fp16(o, o2);
    }
}

// ---------------- launch ----------------
extern "C" void kernel_launch(void* const* d_in, const int* in_sizes, int n_in,
                              void* d_out, int out_size)
{
    const int*   tok      = (const int*)  d_in[0];
    const float* emb      = (const float*)d_in[1];
    const float* in_proj  = (const float*)d_in[2];
    const float* out_proj = (const float*)d_in[3];
    const float* sB       = (const float*)d_in[4];
    const float* sC       = (const float*)d_in[5];
    const float* sD0      = (const float*)d_in[6];
    const float* sD1w     = (const float*)d_in[7];
    const float* sD1b     = (const float*)d_in[8];
    const float* cw       = (const float*)d_in[9];
    const float* cb       = (const float*)d_in[10];
    const float* A_log    = (const float*)d_in[11];
    const float* Dp       = (const float*)d_in[12];
    const float* norm_w   = (const float*)d_in[13];
    const float* norm_f   = (const float*)d_in[14];
    const float* head_w   = (const float*)d_in[15];
    float* out = (float*)d_out;

    float *seq,*ab,*delta,*wpack;
    unsigned *xnf,*sof,*dtf,*wih,*wil,*woh,*wol,*d1h,*d1l,*whf;
    cudaGetSymbolAddress((void**)&seq,   g_seq);
    cudaGetSymbolAddress((void**)&ab,    g_ab);
    cudaGetSymbolAddress((void**)&delta, g_delta);
    cudaGetSymbolAddress((void**)&wpack, g_wpack);
    cudaGetSymbolAddress((void**)&xnf, g_xn_fp);
    cudaGetSymbolAddress((void**)&sof, g_so_fp);
    cudaGetSymbolAddress((void**)&dtf, g_dt_fp);
    cudaGetSymbolAddress((void**)&wih, g_wi_hi); cudaGetSymbolAddress((void**)&wil, g_wi_lo);
    cudaGetSymbolAddress((void**)&woh, g_wo_hi); cudaGetSymbolAddress((void**)&wol, g_wo_lo);
    cudaGetSymbolAddress((void**)&d1h, g_d1_hi); cudaGetSymbolAddress((void**)&d1l, g_d1_lo);
    cudaGetSymbolAddress((void**)&whf, g_wh_fp);

    // order chosen so launch #3 is the in_proj GEMM (ncu capture slot)
    embed_kernel<<<ROWS, 256>>>(tok, emb);                                            // 0
    split16_kernel<<<(NL*2*DM*KW_IN + 255)/256, 256>>>(in_proj, wih, wil,
                                                       NL*2*DM*KW_IN, DIN);           // 1
    rmsnorm_kernel<<<ROWS, 256>>>(seq, norm_w, xnf);                                  // 2
    gemm_f16x2_kernel<<<dim3(ROWS/128, 2*DM/128), 256>>>(
        xnf, wih, wil, ab, ROWS, 2*DM, DIN, nullptr, nullptr, 0);                     // 3
    pack_kernel<<<(NL*128*DM + 255)/256, 256>>>(sB, sC, sD0);                         // 4
    split16_kernel<<<(NL*DIN*KW_DM + 255)/256, 256>>>(out_proj, woh, wol,
                                                      NL*DIN*KW_DM, DM);              // 5
    split16_kernel<<<(NL*DM*KW_DD + 255)/256, 256>>>(sD1w, d1h, d1l,
                                                     NL*DM*KW_DD, DD);                // 6
    fp16_pack_kernel<<<(VOCAB*KW_IN + 255)/256, 256>>>(head_w, whf, VOCAB*KW_IN, DIN);// 7

    for (int l = 0; l < NL; l++){
        if (l > 0){
            rmsnorm_kernel<<<ROWS, 256>>>(seq, norm_w + l*DIN, xnf);
            gemm_f16x2_kernel<<<dim3(ROWS/128, 2*DM/128), 256>>>(
                xnf, wih + (size_t)l*2*DM*KW_IN, wil + (size_t)l*2*DM*KW_IN,
                ab, ROWS, 2*DM, DIN, nullptr, nullptr, 0);
        }
        conv_silu_kernel<<<dim3(DM/256, ROWS), 256>>>(cw + l*DM*4, cb + l*DM);
        small_proj_kernel<<<ROWS/16, 256>>>(wpack + (size_t)l*128*DM);
        // delta = softplus(dt @ sD1w^T + sD1b)   (2048 x 1536, K=96)  [fp16 2-pass]
        gemm_f16x2_kernel<<<dim3(ROWS/128, DM/128), 256>>>(
            dtf, d1h + (size_t)l*DM*KW_DD, d1l + (size_t)l*DM*KW_DD,
            delta, ROWS, DM, DD, sD1b + l*DM, nullptr, 1);
        scan_kernel<<<dim3(DM/8, BB), 128>>>(A_log + (size_t)l*DM*DS, Dp + l*DM);
        // seq = sout @ out_proj^T + seq   (2048 x 768, K=1536)  [fp16 2-pass]
        gemm_f16x2_kernel<<<dim3(ROWS/128, DIN/128), 256>>>(
            sof, woh + (size_t)l*DIN*KW_DM, wol + (size_t)l*DIN*KW_DM,
            seq, ROWS, DIN, DM, nullptr, seq, 0);
    }

    rmsnorm_kernel<<<ROWS, 256>>>(seq, norm_f, xnf);
    // logits = xn @ head_w^T   (2048 x 32000, K=768)  [fp16 single pass]
    gemm_fp16_kernel<<<dim3(ROWS/128, VOCAB/128), 256>>>(
        xnf, whf, out, ROWS, VOCAB, DIN);
}

// round 13
// speedup vs baseline: 1.0023x; 1.0023x over previous
#include <cuda_runtime.h>
#include <cuda_bf16.h>
#include <cuda_fp16.h>
#include <cstdint>

#define BB 2
#define LL 1024
#define DIN 768
#define DM 1536
#define DS 16
#define DD 96
#define NL 4
#define ROWS (BB*LL)   // 2048
#define VOCAB 32000
#define KW_IN (DIN/2)  // 384
#define KW_DM (DM/2)   // 768
#define KW_DD (DD/2)   // 48

// ---------------- scratch (static device globals; no allocation) ----------------
__device__ float g_seq[ROWS*DIN];
__device__ float g_ab [ROWS*2*DM];
__device__ float g_ac [ROWS*DM];
__device__ float g_Bm [ROWS*DS];
__device__ float g_Cm [ROWS*DS];
__device__ float g_delta[ROWS*DM];
__device__ float g_wpack[NL*128*DM];

// packed fp16x2 activations (single array each — weights carry the split)
__device__ unsigned g_xn_fp[ROWS*KW_IN];
__device__ unsigned g_so_fp[ROWS*KW_DM];
__device__ unsigned g_dt_fp[ROWS*KW_DD];
// weights: exact fp16 hi/lo split (hi+lo == fp32 weight to ~22 bits)
__device__ unsigned g_wi_hi[NL*2*DM*KW_IN], g_wi_lo[NL*2*DM*KW_IN];
__device__ unsigned g_wo_hi[NL*DIN*KW_DM],  g_wo_lo[NL*DIN*KW_DM];
__device__ unsigned g_d1_hi[NL*DM*KW_DD],   g_d1_lo[NL*DM*KW_DD];
// head weights single fp16 (1-pass head)
__device__ unsigned g_wh_fp[VOCAB*KW_IN];

__device__ __forceinline__ float siluf(float x){ return x / (1.f + __expf(-x)); }
__device__ __forceinline__ float softplusf(float x){ return fmaxf(x,0.f) + log1pf(expf(-fabsf(x))); }

__device__ __forceinline__ unsigned pack_fp16(float x0, float x1){
    __half h0 = __float2half_rn(x0);
    __half h1 = __float2half_rn(x1);
    return ((unsigned)__half_as_ushort(h1) << 16) | __half_as_ushort(h0);
}
__device__ __forceinline__ unsigned pack_fp16_split(float x0, float x1, unsigned &lopair){
    __half h0 = __float2half_rn(x0);
    __half h1 = __float2half_rn(x1);
    __half l0 = __float2half_rn(x0 - __half2float(h0));
    __half l1 = __float2half_rn(x1 - __half2float(h1));
    lopair = ((unsigned)__half_as_ushort(l1) << 16) | __half_as_ushort(l0);
    return ((unsigned)__half_as_ushort(h1) << 16) | __half_as_ushort(h0);
}

__device__ __forceinline__ void mma_fp16(float* d, const unsigned* a, const unsigned* b){
    asm volatile(
      "mma.sync.aligned.m16n8k16.row.col.f32.f16.f16.f32 "
      "{%0,%1,%2,%3}, {%4,%5,%6,%7}, {%8,%9}, {%0,%1,%2,%3};\n"
      : "+f"(d[0]),"+f"(d[1]),"+f"(d[2]),"+f"(d[3])
      : "r"(a[0]),"r"(a[1]),"r"(a[2]),"r"(a[3]), "r"(b[0]),"r"(b[1]));
}
__device__ __forceinline__ void cp16(unsigned smaddr, const void* g){
    asm volatile("cp.async.cg.shared.global [%0], [%1], 16;" :: "r"(smaddr), "l"(g));
}
__device__ __forceinline__ void ldsm4(unsigned &r0, unsigned &r1, unsigned &r2, unsigned &r3,
                                      unsigned addr){
    asm volatile("ldmatrix.sync.aligned.m8n8.x4.shared.b16 {%0,%1,%2,%3}, [%4];"
      : "=r"(r0),"=r"(r1),"=r"(r2),"=r"(r3) : "r"(addr));
}

// ---------------- weight split: fp32 [Nrows,K] -> packed fp16x2 hi/lo (exact) --------
__global__ void split16_kernel(const float* __restrict__ src, unsigned* __restrict__ hi,
                               unsigned* __restrict__ lo, int totalWords, int K){
    int idx = blockIdx.x*256 + threadIdx.x;
    if (idx >= totalWords) return;
    int Kw = K >> 1;
    int n = idx / Kw, w = idx - n*Kw;
    int k = 2*w;
    unsigned l; unsigned h = pack_fp16_split(src[(size_t)n*K + k], src[(size_t)n*K + k + 1], l);
    hi[idx] = h; lo[idx] = l;
}

// ---------------- fp16 pack: fp32 [Nrows,K] -> packed fp16x2 ----------------
__global__ void fp16_pack_kernel(const float* __restrict__ src, unsigned* __restrict__ dst,
                                 int totalWords, int K){
    int idx = blockIdx.x*256 + threadIdx.x;
    if (idx >= totalWords) return;
    int Kw = K >> 1;
    int n = idx / Kw, w = idx - n*Kw;
    int k = 2*w;
    dst[idx] = pack_fp16(src[(size_t)n*K + k], src[(size_t)n*K + k + 1]);
}

// ---------------- embedding gather ----------------
__global__ void embed_kernel(const int* __restrict__ tok, const float* __restrict__ emb){
    int row = blockIdx.x;
    int t = tok[row];
    for (int c = threadIdx.x; c < DIN; c += blockDim.x)
        g_seq[row*DIN + c] = emb[t*DIN + c];
}

// ---------------- rmsnorm -> packed fp16 output ----------------
__global__ void rmsnorm_kernel(const float* __restrict__ in, const float* __restrict__ w,
                               unsigned* __restrict__ fp){
    int row = blockIdx.x;
    float ss = 0.f;
    #pragma unroll
    for (int i = 0; i < 3; i++){
        float x = in[row*DIN + threadIdx.x + i*256];
        ss += x*x;
    }
    #pragma unroll
    for (int off = 16; off > 0; off >>= 1) ss += __shfl_xor_sync(0xffffffffu, ss, off);
    __shared__ float red[8];
    if ((threadIdx.x & 31) == 0) red[threadIdx.x >> 5] = ss;
    __syncthreads();
    float ms = 0.f;
    #pragma unroll
    for (int i = 0; i < 8; i++) ms += red[i];
    float r = rsqrtf(ms * (1.f/768.f) + 1e-6f);
    for (int p = threadIdx.x; p < KW_IN; p += 256){
        int c = 2*p;
        float y0 = in[row*DIN + c]     * r * w[c];
        float y1 = in[row*DIN + c + 1] * r * w[c+1];
        fp[row*KW_IN + p] = pack_fp16(y0, y1);
    }
}

// ========== 2-pass fp16 GEMM, exact split weights, ldmatrix fragments ==========
// smem rows: 12 words (48B) stride -> LDSM phases hit all 32 banks.
#define RW 12                       // words per row
#define ARW (128*RW)                // words per operand array
#define STW3 (3*ARW)                // words per stage (A,Bhi,Blo)
__global__ void __launch_bounds__(256,2) gemm_f16x2_kernel(
    const unsigned* __restrict__ A,
    const unsigned* __restrict__ Bhi, const unsigned* __restrict__ Blo,
    float* __restrict__ C, int M, int N, int K,
    const float* __restrict__ bias, const float* __restrict__ resid, int act)
{
    __shared__ unsigned sm[2*STW3];
    unsigned smb = (unsigned)__cvta_generic_to_shared(sm);
    int tid = threadIdx.x;
    int lane = tid & 31, warp = tid >> 5;
    int qr = lane >> 2, q = lane & 3;
    int m0 = (warp >> 1) * 32, n0 = (warp & 1) * 64;
    int brow = blockIdx.x * 128, bcol = blockIdx.y * 128;
    int Kw = K >> 1;
    int lrow = tid >> 1;
    unsigned sidx = (unsigned)(lrow*RW + (tid & 1)*4);

    const unsigned* gA  = A   + (size_t)(brow + lrow)*Kw + (tid & 1)*4;
    const unsigned* gBh = Bhi + (size_t)(bcol + lrow)*Kw + (tid & 1)*4;
    const unsigned* gBl = Blo + (size_t)(bcol + lrow)*Kw + (tid & 1)*4;

    // per-lane LDSM addresses (word offsets within a stage), hoisted
    unsigned aOff[2], bhOff[4], blOff[4];
    #pragma unroll
    for (int im = 0; im < 2; im++)
        aOff[im] = (unsigned)((m0 + im*16 + (lane & 15))*RW + (lane >> 4)*4);
    #pragma unroll
    for (int jp = 0; jp < 4; jp++){
        int rowB = n0 + (2*jp + (lane >> 4))*8 + (lane & 7);
        unsigned off = (unsigned)(rowB*RW + ((lane >> 3) & 1)*4);
        bhOff[jp] = ARW   + off;
        blOff[jp] = 2*ARW + off;
    }

    float acc[2][8][4];
    #pragma unroll
    for (int im = 0; im < 2; im++)
        #pragma unroll
        for (int jn = 0; jn < 8; jn++)
            #pragma unroll
            for (int e = 0; e < 4; e++) acc[im][jn][e] = 0.f;

    int kt = K >> 4;

    cp16(smb + sidx*4,             gA);
    cp16(smb + (ARW + sidx)*4,     gBh);
    cp16(smb + (2*ARW + sidx)*4,   gBl);
    asm volatile("cp.async.commit_group;");

    for (int k = 0; k < kt; k++){
        unsigned stB = (k & 1) ? (unsigned)STW3*4 : 0u;
        if (k + 1 < kt){
            unsigned s2 = ((k+1) & 1) ? (unsigned)STW3*4 : 0u;
            size_t off = (size_t)(k+1) * 8;
            cp16(smb + s2 + sidx*4,           gA  + off);
            cp16(smb + s2 + (ARW + sidx)*4,   gBh + off);
            cp16(smb + s2 + (2*ARW + sidx)*4, gBl + off);
            asm volatile("cp.async.commit_group;");
            asm volatile("cp.async.wait_group 1;");
        } else {
            asm volatile("cp.async.wait_group 0;");
        }
        __syncthreads();

        unsigned a[2][4];
        ldsm4(a[0][0], a[0][1], a[0][2], a[0][3], smb + stB + aOff[0]*4);
        ldsm4(a[1][0], a[1][1], a[1][2], a[1][3], smb + stB + aOff[1]*4);
        #pragma unroll
        for (int jp = 0; jp < 4; jp++){
            unsigned bh[4], bl[4];
            ldsm4(bh[0], bh[1], bh[2], bh[3], smb + stB + bhOff[jp]*4);
            ldsm4(bl[0], bl[1], bl[2], bl[3], smb + stB + blOff[jp]*4);
            #pragma unroll
            for (int im = 0; im < 2; im++) mma_fp16(acc[im][2*jp],   a[im], bh + 0);
            #pragma unroll
            for (int im = 0; im < 2; im++) mma_fp16(acc[im][2*jp],   a[im], bl + 0);
            #pragma unroll
            for (int im = 0; im < 2; im++) mma_fp16(acc[im][2*jp+1], a[im], bh + 2);
            #pragma unroll
            for (int im = 0; im < 2; im++) mma_fp16(acc[im][2*jp+1], a[im], bl + 2);
        }
        __syncthreads();
    }

    #pragma unroll
    for (int im = 0; im < 2; im++){
        #pragma unroll
        for (int h = 0; h < 2; h++){
            int m = brow + m0 + im*16 + qr + h*8;
            #pragma unroll
            for (int jn = 0; jn < 8; jn++){
                int n = bcol + n0 + jn*8 + 2*q;
                float v0 = acc[im][jn][h*2 + 0];
                float v1 = acc[im][jn][h*2 + 1];
                if (bias){ v0 += bias[n]; v1 += bias[n+1]; }
                if (act){ v0 = softplusf(v0); v1 = softplusf(v1); }
                if (resid){ v0 += resid[(size_t)m*N + n]; v1 += resid[(size_t)m*N + n + 1]; }
                *(float2*)&C[(size_t)m*N + n] = make_float2(v0, v1);
            }
        }
    }
}

// ========== single-pass fp16 GEMM (head), ldmatrix fragments ==========
#define STW2 (2*ARW)
__global__ void __launch_bounds__(256,2) gemm_fp16_kernel(
    const unsigned* __restrict__ A, const unsigned* __restrict__ B,
    float* __restrict__ C, int M, int N, int K)
{
    __shared__ unsigned sm[2*STW2];
    unsigned smb = (unsigned)__cvta_generic_to_shared(sm);
    int tid = threadIdx.x;
    int lane = tid & 31, warp = tid >> 5;
    int qr = lane >> 2, q = lane & 3;
    int m0 = (warp >> 1) * 32, n0 = (warp & 1) * 64;
    int brow = blockIdx.x * 128, bcol = blockIdx.y * 128;
    int Kw = K >> 1;
    int lrow = tid >> 1;
    unsigned sidx = (unsigned)(lrow*RW + (tid & 1)*4);

    const unsigned* gA = A + (size_t)(brow + lrow)*Kw + (tid & 1)*4;
    const unsigned* gB = B + (size_t)(bcol + lrow)*Kw + (tid & 1)*4;

    unsigned aOff[2], bOff[4];
    #pragma unroll
    for (int im = 0; im < 2; im++)
        aOff[im] = (unsigned)((m0 + im*16 + (lane & 15))*RW + (lane >> 4)*4);
    #pragma unroll
    for (int jp = 0; jp < 4; jp++){
        int rowB = n0 + (2*jp + (lane >> 4))*8 + (lane & 7);
        bOff[jp] = (unsigned)(ARW + rowB*RW + ((lane >> 3) & 1)*4);
    }

    float acc[2][8][4];
    #pragma unroll
    for (int im = 0; im < 2; im++)
        #pragma unroll
        for (int jn = 0; jn < 8; jn++)
            #pragma unroll
            for (int e = 0; e < 4; e++) acc[im][jn][e] = 0.f;

    int kt = K >> 4;

    cp16(smb + sidx*4,         gA);
    cp16(smb + (ARW + sidx)*4, gB);
    asm volatile("cp.async.commit_group;");

    for (int k = 0; k < kt; k++){
        unsigned stB = (k & 1) ? (unsigned)STW2*4 : 0u;
        if (k + 1 < kt){
            unsigned s2 = ((k+1) & 1) ? (unsigned)STW2*4 : 0u;
            size_t off = (size_t)(k+1) * 8;
            cp16(smb + s2 + sidx*4,         gA + off);
            cp16(smb + s2 + (ARW + sidx)*4, gB + off);
            asm volatile("cp.async.commit_group;");
            asm volatile("cp.async.wait_group 1;");
        } else {
            asm volatile("cp.async.wait_group 0;");
        }
        __syncthreads();

        unsigned a[2][4];
        ldsm4(a[0][0], a[0][1], a[0][2], a[0][3], smb + stB + aOff[0]*4);
        ldsm4(a[1][0], a[1][1], a[1][2], a[1][3], smb + stB + aOff[1]*4);
        #pragma unroll
        for (int jp = 0; jp < 4; jp++){
            unsigned b[4];
            ldsm4(b[0], b[1], b[2], b[3], smb + stB + bOff[jp]*4);
            #pragma unroll
            for (int im = 0; im < 2; im++) mma_fp16(acc[im][2*jp],   a[im], b + 0);
            #pragma unroll
            for (int im = 0; im < 2; im++) mma_fp16(acc[im][2*jp+1], a[im], b + 2);
        }
        __syncthreads();
    }

    #pragma unroll
    for (int im = 0; im < 2; im++){
        #pragma unroll
        for (int h = 0; h < 2; h++){
            int m = brow + m0 + im*16 + qr + h*8;
            #pragma unroll
            for (int jn = 0; jn < 8; jn++){
                int n = bcol + n0 + jn*8 + 2*q;
                *(float2*)&C[(size_t)m*N + n] =
                    make_float2(acc[im][jn][h*2 + 0], acc[im][jn][h*2 + 1]);
            }
        }
    }
}

// ---------------- causal depthwise conv (K=4) + SiLU ----------------
__global__ void conv_silu_kernel(const float* __restrict__ cw, const float* __restrict__ cb){
    int d = blockIdx.x * blockDim.x + threadIdx.x;
    int row = blockIdx.y;
    int t = row & (LL-1);
    float4 w = *(const float4*)(cw + d*4);
    float acc = cb[d];
    const float* p = g_ab + (size_t)row*(2*DM) + d;
    if (t >= 3) acc += p[-3*2*DM]*w.x;
    if (t >= 2) acc += p[-2*2*DM]*w.y;
    if (t >= 1) acc += p[-1*2*DM]*w.z;
    acc += p[0]*w.w;
    g_ac[(size_t)row*DM + d] = siluf(acc);
}

// ---------------- pack sB|sC|sD0 into one [NL][128][DM] weight ----------------
__global__ void pack_kernel(const float* __restrict__ sB, const float* __restrict__ sC,
                            const float* __restrict__ sD0){
    int idx = blockIdx.x*256 + threadIdx.x;
    if (idx >= NL*128*DM) return;
    int k = idx % DM;
    int n = (idx / DM) & 127;
    int l = idx / (128*DM);
    float v;
    if (n < 16)      v = sB [((size_t)l*DS + n     )*DM + k];
    else if (n < 32) v = sC [((size_t)l*DS + (n-16))*DM + k];
    else             v = sD0[((size_t)l*DD + (n-32))*DM + k];
    g_wpack[idx] = v;
}

// ---------------- fused small projections: [16 rows] x [128 outs], K=1536 ----------------
#define SP_KC 64
__global__ void __launch_bounds__(256) small_proj_kernel(const float* __restrict__ wp){
    __shared__ float Ws[128][SP_KC+1];
    __shared__ float Xs[16][SP_KC+4];
    int m0  = blockIdx.x * 16;
    int tid = threadIdx.x;
    int n2  = tid & 63;
    int mh  = tid >> 6;
    float acc[2][4] = {{0.f,0.f,0.f,0.f},{0.f,0.f,0.f,0.f}};

    for (int k0 = 0; k0 < DM; k0 += SP_KC){
        #pragma unroll
        for (int j = 0; j < 8; j++){
            int idx = tid + j*256;
            int r = idx >> 4, c4 = (idx & 15) << 2;
            float4 v = *(const float4*)(wp + (size_t)r*DM + k0 + c4);
            Ws[r][c4+0]=v.x; Ws[r][c4+1]=v.y; Ws[r][c4+2]=v.z; Ws[r][c4+3]=v.w;
        }
        {
            int r = tid >> 4, c4 = (tid & 15) << 2;
            float4 v = *(const float4*)(g_ac + (size_t)(m0+r)*DM + k0 + c4);
            Xs[r][c4+0]=v.x; Xs[r][c4+1]=v.y; Xs[r][c4+2]=v.z; Xs[r][c4+3]=v.w;
        }
        __syncthreads();
        #pragma unroll 8
        for (int kk = 0; kk < SP_KC; kk++){
            float w0 = Ws[2*n2][kk], w1 = Ws[2*n2+1][kk];
            #pragma unroll
            for (int i = 0; i < 4; i++){
                float x = Xs[mh*4+i][kk];
                acc[0][i] += w0*x;
                acc[1][i] += w1*x;
            }
        }
        __syncthreads();
    }
    #pragma unroll
    for (int i = 0; i < 4; i++){
        int m = m0 + mh*4 + i;
        int n = 2*n2;
        if (n2 < 8){
            g_Bm[m*DS + n]   = acc[0][i];
            g_Bm[m*DS + n+1] = acc[1][i];
        } else if (n2 < 16){
            g_Cm[m*DS + (n-16)]   = acc[0][i];
            g_Cm[m*DS + (n-16)+1] = acc[1][i];
        } else {
            g_dt_fp[m*KW_DD + (n2-16)] = pack_fp16(acc[0][i], acc[1][i]);
        }
    }
}

// ---------------- selective scan, prefetch ring depth 8; fp16 packed out -----------
#define PD 8
__global__ void scan_kernel(const float* __restrict__ A_log, const float* __restrict__ Dp){
    int lane = threadIdx.x & 31, warp = threadIdx.x >> 5;
    int s = lane & 15;
    int d = blockIdx.x*8 + warp*2 + (lane >> 4);
    int b = blockIdx.y;
    float Acoef = -expf(A_log[d*DS + s]);
    float Dv = Dp[d];
    const float* pd = g_delta + (size_t)(b*LL)*DM + d;
    const float* pa = g_ac    + (size_t)(b*LL)*DM + d;
    const float* pg = g_ab    + (size_t)(b*LL)*(2*DM) + DM + d;
    const float* pB = g_Bm    + (size_t)(b*LL)*DS + s;
    const float* pC = g_Cm    + (size_t)(b*LL)*DS + s;
    float f_d[PD], f_a[PD], f_g[PD], f_B[PD], f_C[PD];
    #pragma unroll
    for (int i = 0; i < PD; i++){
        f_d[i] = pd[(size_t)i*DM];
        f_a[i] = pa[(size_t)i*DM];
        f_g[i] = pg[(size_t)i*2*DM];
        f_B[i] = pB[(size_t)i*DS];
        f_C[i] = pC[(size_t)i*DS];
    }
    float h = 0.f;
    int p = blockIdx.x*4 + warp;        // d-pair index within KW_DM
    int wbase = (b*LL)*KW_DM + p;
    #pragma unroll 8
    for (int t = 0; t < LL; t++){
        int sl = t & (PD-1);
        float dc = f_d[sl], a_c = f_a[sl], gc = f_g[sl];
        float bc = f_B[sl], cc = f_C[sl];
        int tn = t + PD;
        if (tn < LL){
            f_d[sl] = pd[(size_t)tn*DM];
            f_a[sl] = pa[(size_t)tn*DM];
            f_g[sl] = pg[(size_t)tn*2*DM];
            f_B[sl] = pB[(size_t)tn*DS];
            f_C[sl] = pC[(size_t)tn*DS];
        }
        h = __expf(dc*Acoef)*h + dc*bc*a_c;
        float c = h*cc;
        c += __shfl_xor_sync(0xffffffffu, c, 8);
        c += __shfl_xor_sync(0xffffffffu, c, 4);
        c += __shfl_xor_sync(0xffffffffu, c, 2);
        c += __shfl_xor_sync(0xffffffffu, c, 1);
        float o = (c + Dv*a_c) * siluf(gc);
        float o2 = __shfl_xor_sync(0xffffffffu, o, 16);
        if (lane == 0)
            g_so_fp[wbase + t*KW_DM] = pack_fp16(o, o2);
    }
}

// ---------------- launch ----------------
extern "C" void kernel_launch(void* const* d_in, const int* in_sizes, int n_in,
                              void* d_out, int out_size)
{
    const int*   tok      = (const int*)  d_in[0];
    const float* emb      = (const float*)d_in[1];
    const float* in_proj  = (const float*)d_in[2];
    const float* out_proj = (const float*)d_in[3];
    const float* sB       = (const float*)d_in[4];
    const float* sC       = (const float*)d_in[5];
    const float* sD0      = (const float*)d_in[6];
    const float* sD1w     = (const float*)d_in[7];
    const float* sD1b     = (const float*)d_in[8];
    const float* cw       = (const float*)d_in[9];
    const float* cb       = (const float*)d_in[10];
    const float* A_log    = (const float*)d_in[11];
    const float* Dp       = (const float*)d_in[12];
    const float* norm_w   = (const float*)d_in[13];
    const float* norm_f   = (const float*)d_in[14];
    const float* head_w   = (const float*)d_in[15];
    float* out = (float*)d_out;

    float *seq,*ab,*delta,*wpack;
    unsigned *xnf,*sof,*dtf,*wih,*wil,*woh,*wol,*d1h,*d1l,*whf;
    cudaGetSymbolAddress((void**)&seq,   g_seq);
    cudaGetSymbolAddress((void**)&ab,    g_ab);
    cudaGetSymbolAddress((void**)&delta, g_delta);
    cudaGetSymbolAddress((void**)&wpack, g_wpack);
    cudaGetSymbolAddress((void**)&xnf, g_xn_fp);
    cudaGetSymbolAddress((void**)&sof, g_so_fp);
    cudaGetSymbolAddress((void**)&dtf, g_dt_fp);
    cudaGetSymbolAddress((void**)&wih, g_wi_hi); cudaGetSymbolAddress((void**)&wil, g_wi_lo);
    cudaGetSymbolAddress((void**)&woh, g_wo_hi); cudaGetSymbolAddress((void**)&wol, g_wo_lo);
    cudaGetSymbolAddress((void**)&d1h, g_d1_hi); cudaGetSymbolAddress((void**)&d1l, g_d1_lo);
    cudaGetSymbolAddress((void**)&whf, g_wh_fp);

    // order chosen so launch #3 is the in_proj GEMM (ncu capture slot)
    embed_kernel<<<ROWS, 256>>>(tok, emb);                                            // 0
    split16_kernel<<<(NL*2*DM*KW_IN + 255)/256, 256>>>(in_proj, wih, wil,
                                                       NL*2*DM*KW_IN, DIN);           // 1
    rmsnorm_kernel<<<ROWS, 256>>>(seq, norm_w, xnf);                                  // 2
    gemm_f16x2_kernel<<<dim3(ROWS/128, 2*DM/128), 256>>>(
        xnf, wih, wil, ab, ROWS, 2*DM, DIN, nullptr, nullptr, 0);                     // 3
    pack_kernel<<<(NL*128*DM + 255)/256, 256>>>(sB, sC, sD0);                         // 4
    split16_kernel<<<(NL*DIN*KW_DM + 255)/256, 256>>>(out_proj, woh, wol,
                                                      NL*DIN*KW_DM, DM);              // 5
    split16_kernel<<<(NL*DM*KW_DD + 255)/256, 256>>>(sD1w, d1h, d1l,
                                                     NL*DM*KW_DD, DD);                // 6
    fp16_pack_kernel<<<(VOCAB*KW_IN + 255)/256, 256>>>(head_w, whf, VOCAB*KW_IN, DIN);// 7

    for (int l = 0; l < NL; l++){
        if (l > 0){
            rmsnorm_kernel<<<ROWS, 256>>>(seq, norm_w + l*DIN, xnf);
            gemm_f16x2_kernel<<<dim3(ROWS/128, 2*DM/128), 256>>>(
                xnf, wih + (size_t)l*2*DM*KW_IN, wil + (size_t)l*2*DM*KW_IN,
                ab, ROWS, 2*DM, DIN, nullptr, nullptr, 0);
        }
        conv_silu_kernel<<<dim3(DM/256, ROWS), 256>>>(cw + l*DM*4, cb + l*DM);
        small_proj_kernel<<<ROWS/16, 256>>>(wpack + (size_t)l*128*DM);
        // delta = softplus(dt @ sD1w^T + sD1b)   (2048 x 1536, K=96)  [fp16 2-pass]
        gemm_f16x2_kernel<<<dim3(ROWS/128, DM/128), 256>>>(
            dtf, d1h + (size_t)l*DM*KW_DD, d1l + (size_t)l*DM*KW_DD,
            delta, ROWS, DM, DD, sD1b + l*DM, nullptr, 1);
        scan_kernel<<<dim3(DM/8, BB), 128>>>(A_log + (size_t)l*DM*DS, Dp + l*DM);
        // seq = sout @ out_proj^T + seq   (2048 x 768, K=1536)  [fp16 2-pass]
        gemm_f16x2_kernel<<<dim3(ROWS/128, DIN/128), 256>>>(
            sof, woh + (size_t)l*DIN*KW_DM, wol + (size_t)l*DIN*KW_DM,
            seq, ROWS, DIN, DM, nullptr, seq, 0);
    }

    rmsnorm_kernel<<<ROWS, 256>>>(seq, norm_f, xnf);
    // logits = xn @ head_w^T   (2048 x 32000, K=768)  [fp16 single pass]
    gemm_fp16_kernel<<<dim3(ROWS/128, VOCAB/128), 256>>>(
        xnf, whf, out, ROWS, VOCAB, DIN);
}

// round 14
// speedup vs baseline: 1.0033x; 1.0010x over previous
#include <cuda_runtime.h>
#include <cuda_bf16.h>
#include <cuda_fp16.h>
#include <cstdint>

#define BB 2
#define LL 1024
#define DIN 768
#define DM 1536
#define DS 16
#define DD 96
#define NL 4
#define ROWS (BB*LL)   // 2048
#define VOCAB 32000
#define KW_IN (DIN/2)  // 384
#define KW_DM (DM/2)   // 768
#define KW_DD (DD/2)   // 48

// ---------------- scratch (static device globals; no allocation) ----------------
__device__ float g_seq[ROWS*DIN];
__device__ float g_ab [ROWS*2*DM];
__device__ float g_ac [ROWS*DM];
__device__ float g_Bm [ROWS*DS];
__device__ float g_Cm [ROWS*DS];
__device__ float g_delta[ROWS*DM];
__device__ float g_wpack[NL*128*DM];

// packed fp16x2 activations (single array each — weights carry the split)
__device__ unsigned g_xn_fp[ROWS*KW_IN];
__device__ unsigned g_so_fp[ROWS*KW_DM];
__device__ unsigned g_dt_fp[ROWS*KW_DD];
// weights: exact fp16 hi/lo split (hi+lo == fp32 weight to ~22 bits)
__device__ unsigned g_wi_hi[NL*2*DM*KW_IN], g_wi_lo[NL*2*DM*KW_IN];
__device__ unsigned g_wo_hi[NL*DIN*KW_DM],  g_wo_lo[NL*DIN*KW_DM];
__device__ unsigned g_d1_hi[NL*DM*KW_DD],   g_d1_lo[NL*DM*KW_DD];
// head weights single fp16 (1-pass head)
__device__ unsigned g_wh_fp[VOCAB*KW_IN];

__device__ __forceinline__ float siluf(float x){ return x / (1.f + __expf(-x)); }
__device__ __forceinline__ float softplusf(float x){ return fmaxf(x,0.f) + log1pf(expf(-fabsf(x))); }

__device__ __forceinline__ unsigned pack_fp16(float x0, float x1){
    __half h0 = __float2half_rn(x0);
    __half h1 = __float2half_rn(x1);
    return ((unsigned)__half_as_ushort(h1) << 16) | __half_as_ushort(h0);
}
__device__ __forceinline__ unsigned pack_fp16_split(float x0, float x1, unsigned &lopair){
    __half h0 = __float2half_rn(x0);
    __half h1 = __float2half_rn(x1);
    __half l0 = __float2half_rn(x0 - __half2float(h0));
    __half l1 = __float2half_rn(x1 - __half2float(h1));
    lopair = ((unsigned)__half_as_ushort(l1) << 16) | __half_as_ushort(l0);
    return ((unsigned)__half_as_ushort(h1) << 16) | __half_as_ushort(h0);
}

__device__ __forceinline__ void mma_fp16(float* d, const unsigned* a, const unsigned* b){
    asm volatile(
      "mma.sync.aligned.m16n8k16.row.col.f32.f16.f16.f32 "
      "{%0,%1,%2,%3}, {%4,%5,%6,%7}, {%8,%9}, {%0,%1,%2,%3};\n"
      : "+f"(d[0]),"+f"(d[1]),"+f"(d[2]),"+f"(d[3])
      : "r"(a[0]),"r"(a[1]),"r"(a[2]),"r"(a[3]), "r"(b[0]),"r"(b[1]));
}
__device__ __forceinline__ void cp16(unsigned smaddr, const void* g){
    asm volatile("cp.async.cg.shared.global [%0], [%1], 16;" :: "r"(smaddr), "l"(g));
}
__device__ __forceinline__ void ldsm4(unsigned &r0, unsigned &r1, unsigned &r2, unsigned &r3,
                                      unsigned addr){
    asm volatile("ldmatrix.sync.aligned.m8n8.x4.shared.b16 {%0,%1,%2,%3}, [%4];"
      : "=r"(r0),"=r"(r1),"=r"(r2),"=r"(r3) : "r"(addr));
}

// ---------------- weight split: fp32 [Nrows,K] -> packed fp16x2 hi/lo (exact) --------
__global__ void split16_kernel(const float* __restrict__ src, unsigned* __restrict__ hi,
                               unsigned* __restrict__ lo, int totalWords, int K){
    int idx = blockIdx.x*256 + threadIdx.x;
    if (idx >= totalWords) return;
    int Kw = K >> 1;
    int n = idx / Kw, w = idx - n*Kw;
    int k = 2*w;
    unsigned l; unsigned h = pack_fp16_split(src[(size_t)n*K + k], src[(size_t)n*K + k + 1], l);
    hi[idx] = h; lo[idx] = l;
}

// ---------------- fp16 pack: fp32 [Nrows,K] -> packed fp16x2 ----------------
__global__ void fp16_pack_kernel(const float* __restrict__ src, unsigned* __restrict__ dst,
                                 int totalWords, int K){
    int idx = blockIdx.x*256 + threadIdx.x;
    if (idx >= totalWords) return;
    int Kw = K >> 1;
    int n = idx / Kw, w = idx - n*Kw;
    int k = 2*w;
    dst[idx] = pack_fp16(src[(size_t)n*K + k], src[(size_t)n*K + k + 1]);
}

// ---------------- embedding gather ----------------
__global__ void embed_kernel(const int* __restrict__ tok, const float* __restrict__ emb){
    int row = blockIdx.x;
    int t = tok[row];
    for (int c = threadIdx.x; c < DIN; c += blockDim.x)
        g_seq[row*DIN + c] = emb[t*DIN + c];
}

// ---------------- rmsnorm -> packed fp16 output ----------------
__global__ void rmsnorm_kernel(const float* __restrict__ in, const float* __restrict__ w,
                               unsigned* __restrict__ fp){
    int row = blockIdx.x;
    float ss = 0.f;
    #pragma unroll
    for (int i = 0; i < 3; i++){
        float x = in[row*DIN + threadIdx.x + i*256];
        ss += x*x;
    }
    #pragma unroll
    for (int off = 16; off > 0; off >>= 1) ss += __shfl_xor_sync(0xffffffffu, ss, off);
    __shared__ float red[8];
    if ((threadIdx.x & 31) == 0) red[threadIdx.x >> 5] = ss;
    __syncthreads();
    float ms = 0.f;
    #pragma unroll
    for (int i = 0; i < 8; i++) ms += red[i];
    float r = rsqrtf(ms * (1.f/768.f) + 1e-6f);
    for (int p = threadIdx.x; p < KW_IN; p += 256){
        int c = 2*p;
        float y0 = in[row*DIN + c]     * r * w[c];
        float y1 = in[row*DIN + c + 1] * r * w[c+1];
        fp[row*KW_IN + p] = pack_fp16(y0, y1);
    }
}

// ========== 2-pass fp16 GEMM, exact split weights, ldmatrix fragments ==========
// smem rows: 12 words (48B) stride -> LDSM phases hit all 32 banks.
#define RW 12                       // words per row
#define ARW (128*RW)                // words per operand array
#define STW3 (3*ARW)                // words per stage (A,Bhi,Blo)
__global__ void __launch_bounds__(256,2) gemm_f16x2_kernel(
    const unsigned* __restrict__ A,
    const unsigned* __restrict__ Bhi, const unsigned* __restrict__ Blo,
    float* __restrict__ C, int M, int N, int K,
    const float* __restrict__ bias, const float* __restrict__ resid, int act)
{
    __shared__ unsigned sm[2*STW3];
    unsigned smb = (unsigned)__cvta_generic_to_shared(sm);
    int tid = threadIdx.x;
    int lane = tid & 31, warp = tid >> 5;
    int qr = lane >> 2, q = lane & 3;
    int m0 = (warp >> 1) * 32, n0 = (warp & 1) * 64;
    int brow = blockIdx.x * 128, bcol = blockIdx.y * 128;
    int Kw = K >> 1;
    int lrow = tid >> 1;
    unsigned sidx = (unsigned)(lrow*RW + (tid & 1)*4);

    const unsigned* gA  = A   + (size_t)(brow + lrow)*Kw + (tid & 1)*4;
    const unsigned* gBh = Bhi + (size_t)(bcol + lrow)*Kw + (tid & 1)*4;
    const unsigned* gBl = Blo + (size_t)(bcol + lrow)*Kw + (tid & 1)*4;

    // per-lane LDSM addresses (word offsets within a stage), hoisted
    unsigned aOff[2], bhOff[4], blOff[4];
    #pragma unroll
    for (int im = 0; im < 2; im++)
        aOff[im] = (unsigned)((m0 + im*16 + (lane & 15))*RW + (lane >> 4)*4);
    #pragma unroll
    for (int jp = 0; jp < 4; jp++){
        int rowB = n0 + (2*jp + (lane >> 4))*8 + (lane & 7);
        unsigned off = (unsigned)(rowB*RW + ((lane >> 3) & 1)*4);
        bhOff[jp] = ARW   + off;
        blOff[jp] = 2*ARW + off;
    }

    float acc[2][8][4];
    #pragma unroll
    for (int im = 0; im < 2; im++)
        #pragma unroll
        for (int jn = 0; jn < 8; jn++)
            #pragma unroll
            for (int e = 0; e < 4; e++) acc[im][jn][e] = 0.f;

    int kt = K >> 4;

    cp16(smb + sidx*4,             gA);
    cp16(smb + (ARW + sidx)*4,     gBh);
    cp16(smb + (2*ARW + sidx)*4,   gBl);
    asm volatile("cp.async.commit_group;");

    for (int k = 0; k < kt; k++){
        unsigned stB = (k & 1) ? (unsigned)STW3*4 : 0u;
        if (k + 1 < kt){
            unsigned s2 = ((k+1) & 1) ? (unsigned)STW3*4 : 0u;
            size_t off = (size_t)(k+1) * 8;
            cp16(smb + s2 + sidx*4,           gA  + off);
            cp16(smb + s2 + (ARW + sidx)*4,   gBh + off);
            cp16(smb + s2 + (2*ARW + sidx)*4, gBl + off);
            asm volatile("cp.async.commit_group;");
            asm volatile("cp.async.wait_group 1;");
        } else {
            asm volatile("cp.async.wait_group 0;");
        }
        __syncthreads();

        unsigned a[2][4];
        ldsm4(a[0][0], a[0][1], a[0][2], a[0][3], smb + stB + aOff[0]*4);
        ldsm4(a[1][0], a[1][1], a[1][2], a[1][3], smb + stB + aOff[1]*4);
        #pragma unroll
        for (int jp = 0; jp < 4; jp++){
            unsigned bh[4], bl[4];
            ldsm4(bh[0], bh[1], bh[2], bh[3], smb + stB + bhOff[jp]*4);
            ldsm4(bl[0], bl[1], bl[2], bl[3], smb + stB + blOff[jp]*4);
            #pragma unroll
            for (int im = 0; im < 2; im++) mma_fp16(acc[im][2*jp],   a[im], bh + 0);
            #pragma unroll
            for (int im = 0; im < 2; im++) mma_fp16(acc[im][2*jp],   a[im], bl + 0);
            #pragma unroll
            for (int im = 0; im < 2; im++) mma_fp16(acc[im][2*jp+1], a[im], bh + 2);
            #pragma unroll
            for (int im = 0; im < 2; im++) mma_fp16(acc[im][2*jp+1], a[im], bl + 2);
        }
        __syncthreads();
    }

    #pragma unroll
    for (int im = 0; im < 2; im++){
        #pragma unroll
        for (int h = 0; h < 2; h++){
            int m = brow + m0 + im*16 + qr + h*8;
            #pragma unroll
            for (int jn = 0; jn < 8; jn++){
                int n = bcol + n0 + jn*8 + 2*q;
                float v0 = acc[im][jn][h*2 + 0];
                float v1 = acc[im][jn][h*2 + 1];
                if (bias){ v0 += bias[n]; v1 += bias[n+1]; }
                if (act){ v0 = softplusf(v0); v1 = softplusf(v1); }
                if (resid){ v0 += resid[(size_t)m*N + n]; v1 += resid[(size_t)m*N + n + 1]; }
                *(float2*)&C[(size_t)m*N + n] = make_float2(v0, v1);
            }
        }
    }
}

// ========== single-pass fp16 GEMM (head), ldmatrix fragments ==========
#define STW2 (2*ARW)
__global__ void __launch_bounds__(256,2) gemm_fp16_kernel(
    const unsigned* __restrict__ A, const unsigned* __restrict__ B,
    float* __restrict__ C, int M, int N, int K)
{
    __shared__ unsigned sm[2*STW2];
    unsigned smb = (unsigned)__cvta_generic_to_shared(sm);
    int tid = threadIdx.x;
    int lane = tid & 31, warp = tid >> 5;
    int qr = lane >> 2, q = lane & 3;
    int m0 = (warp >> 1) * 32, n0 = (warp & 1) * 64;
    int brow = blockIdx.x * 128, bcol = blockIdx.y * 128;
    int Kw = K >> 1;
    int lrow = tid >> 1;
    unsigned sidx = (unsigned)(lrow*RW + (tid & 1)*4);

    const unsigned* gA = A + (size_t)(brow + lrow)*Kw + (tid & 1)*4;
    const unsigned* gB = B + (size_t)(bcol + lrow)*Kw + (tid & 1)*4;

    unsigned aOff[2], bOff[4];
    #pragma unroll
    for (int im = 0; im < 2; im++)
        aOff[im] = (unsigned)((m0 + im*16 + (lane & 15))*RW + (lane >> 4)*4);
    #pragma unroll
    for (int jp = 0; jp < 4; jp++){
        int rowB = n0 + (2*jp + (lane >> 4))*8 + (lane & 7);
        bOff[jp] = (unsigned)(ARW + rowB*RW + ((lane >> 3) & 1)*4);
    }

    float acc[2][8][4];
    #pragma unroll
    for (int im = 0; im < 2; im++)
        #pragma unroll
        for (int jn = 0; jn < 8; jn++)
            #pragma unroll
            for (int e = 0; e < 4; e++) acc[im][jn][e] = 0.f;

    int kt = K >> 4;

    cp16(smb + sidx*4,         gA);
    cp16(smb + (ARW + sidx)*4, gB);
    asm volatile("cp.async.commit_group;");

    for (int k = 0; k < kt; k++){
        unsigned stB = (k & 1) ? (unsigned)STW2*4 : 0u;
        if (k + 1 < kt){
            unsigned s2 = ((k+1) & 1) ? (unsigned)STW2*4 : 0u;
            size_t off = (size_t)(k+1) * 8;
            cp16(smb + s2 + sidx*4,         gA + off);
            cp16(smb + s2 + (ARW + sidx)*4, gB + off);
            asm volatile("cp.async.commit_group;");
            asm volatile("cp.async.wait_group 1;");
        } else {
            asm volatile("cp.async.wait_group 0;");
        }
        __syncthreads();

        unsigned a[2][4];
        ldsm4(a[0][0], a[0][1], a[0][2], a[0][3], smb + stB + aOff[0]*4);
        ldsm4(a[1][0], a[1][1], a[1][2], a[1][3], smb + stB + aOff[1]*4);
        #pragma unroll
        for (int jp = 0; jp < 4; jp++){
            unsigned b[4];
            ldsm4(b[0], b[1], b[2], b[3], smb + stB + bOff[jp]*4);
            #pragma unroll
            for (int im = 0; im < 2; im++) mma_fp16(acc[im][2*jp],   a[im], b + 0);
            #pragma unroll
            for (int im = 0; im < 2; im++) mma_fp16(acc[im][2*jp+1], a[im], b + 2);
        }
        __syncthreads();
    }

    #pragma unroll
    for (int im = 0; im < 2; im++){
        #pragma unroll
        for (int h = 0; h < 2; h++){
            int m = brow + m0 + im*16 + qr + h*8;
            #pragma unroll
            for (int jn = 0; jn < 8; jn++){
                int n = bcol + n0 + jn*8 + 2*q;
                *(float2*)&C[(size_t)m*N + n] =
                    make_float2(acc[im][jn][h*2 + 0], acc[im][jn][h*2 + 1]);
            }
        }
    }
}

// ---------------- causal depthwise conv (K=4) + SiLU ----------------
__global__ void conv_silu_kernel(const float* __restrict__ cw, const float* __restrict__ cb){
    int d = blockIdx.x * blockDim.x + threadIdx.x;
    int row = blockIdx.y;
    int t = row & (LL-1);
    float4 w = *(const float4*)(cw + d*4);
    float acc = cb[d];
    const float* p = g_ab + (size_t)row*(2*DM) + d;
    if (t >= 3) acc += p[-3*2*DM]*w.x;
    if (t >= 2) acc += p[-2*2*DM]*w.y;
    if (t >= 1) acc += p[-1*2*DM]*w.z;
    acc += p[0]*w.w;
    g_ac[(size_t)row*DM + d] = siluf(acc);
}

// ---------------- pack sB|sC|sD0 into one [NL][128][DM] weight ----------------
__global__ void pack_kernel(const float* __restrict__ sB, const float* __restrict__ sC,
                            const float* __restrict__ sD0){
    int idx = blockIdx.x*256 + threadIdx.x;
    if (idx >= NL*128*DM) return;
    int k = idx % DM;
    int n = (idx / DM) & 127;
    int l = idx / (128*DM);
    float v;
    if (n < 16)      v = sB [((size_t)l*DS + n     )*DM + k];
    else if (n < 32) v = sC [((size_t)l*DS + (n-16))*DM + k];
    else             v = sD0[((size_t)l*DD + (n-32))*DM + k];
    g_wpack[idx] = v;
}

// ---------------- fused small projections: [16 rows] x [128 outs], K=1536 ----------------
#define SP_KC 64
__global__ void __launch_bounds__(256) small_proj_kernel(const float* __restrict__ wp){
    __shared__ float Ws[128][SP_KC+1];
    __shared__ float Xs[16][SP_KC+4];
    int m0  = blockIdx.x * 16;
    int tid = threadIdx.x;
    int n2  = tid & 63;
    int mh  = tid >> 6;
    float acc[2][4] = {{0.f,0.f,0.f,0.f},{0.f,0.f,0.f,0.f}};

    for (int k0 = 0; k0 < DM; k0 += SP_KC){
        #pragma unroll
        for (int j = 0; j < 8; j++){
            int idx = tid + j*256;
            int r = idx >> 4, c4 = (idx & 15) << 2;
            float4 v = *(const float4*)(wp + (size_t)r*DM + k0 + c4);
            Ws[r][c4+0]=v.x; Ws[r][c4+1]=v.y; Ws[r][c4+2]=v.z; Ws[r][c4+3]=v.w;
        }
        {
            int r = tid >> 4, c4 = (tid & 15) << 2;
            float4 v = *(const float4*)(g_ac + (size_t)(m0+r)*DM + k0 + c4);
            Xs[r][c4+0]=v.x; Xs[r][c4+1]=v.y; Xs[r][c4+2]=v.z; Xs[r][c4+3]=v.w;
        }
        __syncthreads();
        #pragma unroll 8
        for (int kk = 0; kk < SP_KC; kk++){
            float w0 = Ws[2*n2][kk], w1 = Ws[2*n2+1][kk];
            #pragma unroll
            for (int i = 0; i < 4; i++){
                float x = Xs[mh*4+i][kk];
                acc[0][i] += w0*x;
                acc[1][i] += w1*x;
            }
        }
        __syncthreads();
    }
    #pragma unroll
    for (int i = 0; i < 4; i++){
        int m = m0 + mh*4 + i;
        int n = 2*n2;
        if (n2 < 8){
            g_Bm[m*DS + n]   = acc[0][i];
            g_Bm[m*DS + n+1] = acc[1][i];
        } else if (n2 < 16){
            g_Cm[m*DS + (n-16)]   = acc[0][i];
            g_Cm[m*DS + (n-16)+1] = acc[1][i];
        } else {
            g_dt_fp[m*KW_DD + (n2-16)] = pack_fp16(acc[0][i], acc[1][i]);
        }
    }
}

// ---------------- selective scan, prefetch ring depth 8; fp16 packed out -----------
#define PD 8
__global__ void scan_kernel(const float* __restrict__ A_log, const float* __restrict__ Dp){
    int lane = threadIdx.x & 31, warp = threadIdx.x >> 5;
    int s = lane & 15;
    int d = blockIdx.x*8 + warp*2 + (lane >> 4);
    int b = blockIdx.y;
    float Acoef = -expf(A_log[d*DS + s]);
    float Dv = Dp[d];
    const float* pd = g_delta + (size_t)(b*LL)*DM + d;
    const float* pa = g_ac    + (size_t)(b*LL)*DM + d;
    const float* pg = g_ab    + (size_t)(b*LL)*(2*DM) + DM + d;
    const float* pB = g_Bm    + (size_t)(b*LL)*DS + s;
    const float* pC = g_Cm    + (size_t)(b*LL)*DS + s;
    float f_d[PD], f_a[PD], f_g[PD], f_B[PD], f_C[PD];
    #pragma unroll
    for (int i = 0; i < PD; i++){
        f_d[i] = pd[(size_t)i*DM];
        f_a[i] = pa[(size_t)i*DM];
        f_g[i] = pg[(size_t)i*2*DM];
        f_B[i] = pB[(size_t)i*DS];
        f_C[i] = pC[(size_t)i*DS];
    }
    float h = 0.f;
    int p = blockIdx.x*4 + warp;        // d-pair index within KW_DM
    int wbase = (b*LL)*KW_DM + p;
    #pragma unroll 8
    for (int t = 0; t < LL; t++){
        int sl = t & (PD-1);
        float dc = f_d[sl], a_c = f_a[sl], gc = f_g[sl];
        float bc = f_B[sl], cc = f_C[sl];
        int tn = t + PD;
        if (tn < LL){
            f_d[sl] = pd[(size_t)tn*DM];
            f_a[sl] = pa[(size_t)tn*DM];
            f_g[sl] = pg[(size_t)tn*2*DM];
            f_B[sl] = pB[(size_t)tn*DS];
            f_C[sl] = pC[(size_t)tn*DS];
        }
        h = __expf(dc*Acoef)*h + dc*bc*a_c;
        float c = h*cc;
        c += __shfl_xor_sync(0xffffffffu, c, 8);
        c += __shfl_xor_sync(0xffffffffu, c, 4);
        c += __shfl_xor_sync(0xffffffffu, c, 2);
        c += __shfl_xor_sync(0xffffffffu, c, 1);
        float o = (c + Dv*a_c) * siluf(gc);
        float o2 = __shfl_xor_sync(0xffffffffu, o, 16);
        if (lane == 0)
            g_so_fp[wbase + t*KW_DM] = pack_fp16(o, o2);
    }
}

// ---------------- launch ----------------
extern "C" void kernel_launch(void* const* d_in, const int* in_sizes, int n_in,
                              void* d_out, int out_size)
{
    const int*   tok      = (const int*)  d_in[0];
    const float* emb      = (const float*)d_in[1];
    const float* in_proj  = (const float*)d_in[2];
    const float* out_proj = (const float*)d_in[3];
    const float* sB       = (const float*)d_in[4];
    const float* sC       = (const float*)d_in[5];
    const float* sD0      = (const float*)d_in[6];
    const float* sD1w     = (const float*)d_in[7];
    const float* sD1b     = (const float*)d_in[8];
    const float* cw       = (const float*)d_in[9];
    const float* cb       = (const float*)d_in[10];
    const float* A_log    = (const float*)d_in[11];
    const float* Dp       = (const float*)d_in[12];
    const float* norm_w   = (const float*)d_in[13];
    const float* norm_f   = (const float*)d_in[14];
    const float* head_w   = (const float*)d_in[15];
    float* out = (float*)d_out;

    float *seq,*ab,*delta,*wpack;
    unsigned *xnf,*sof,*dtf,*wih,*wil,*woh,*wol,*d1h,*d1l,*whf;
    cudaGetSymbolAddress((void**)&seq,   g_seq);
    cudaGetSymbolAddress((void**)&ab,    g_ab);
    cudaGetSymbolAddress((void**)&delta, g_delta);
    cudaGetSymbolAddress((void**)&wpack, g_wpack);
    cudaGetSymbolAddress((void**)&xnf, g_xn_fp);
    cudaGetSymbolAddress((void**)&sof, g_so_fp);
    cudaGetSymbolAddress((void**)&dtf, g_dt_fp);
    cudaGetSymbolAddress((void**)&wih, g_wi_hi); cudaGetSymbolAddress((void**)&wil, g_wi_lo);
    cudaGetSymbolAddress((void**)&woh, g_wo_hi); cudaGetSymbolAddress((void**)&wol, g_wo_lo);
    cudaGetSymbolAddress((void**)&d1h, g_d1_hi); cudaGetSymbolAddress((void**)&d1l, g_d1_lo);
    cudaGetSymbolAddress((void**)&whf, g_wh_fp);

    // order chosen so launch #3 is the in_proj GEMM (ncu capture slot)
    embed_kernel<<<ROWS, 256>>>(tok, emb);                                            // 0
    split16_kernel<<<(NL*2*DM*KW_IN + 255)/256, 256>>>(in_proj, wih, wil,
                                                       NL*2*DM*KW_IN, DIN);           // 1
    rmsnorm_kernel<<<ROWS, 256>>>(seq, norm_w, xnf);                                  // 2
    gemm_f16x2_kernel<<<dim3(ROWS/128, 2*DM/128), 256>>>(
        xnf, wih, wil, ab, ROWS, 2*DM, DIN, nullptr, nullptr, 0);                     // 3
    pack_kernel<<<(NL*128*DM + 255)/256, 256>>>(sB, sC, sD0);                         // 4
    split16_kernel<<<(NL*DIN*KW_DM + 255)/256, 256>>>(out_proj, woh, wol,
                                                      NL*DIN*KW_DM, DM);              // 5
    split16_kernel<<<(NL*DM*KW_DD + 255)/256, 256>>>(sD1w, d1h, d1l,
                                                     NL*DM*KW_DD, DD);                // 6
    fp16_pack_kernel<<<(VOCAB*KW_IN + 255)/256, 256>>>(head_w, whf, VOCAB*KW_IN, DIN);// 7

    for (int l = 0; l < NL; l++){
        if (l > 0){
            rmsnorm_kernel<<<ROWS, 256>>>(seq, norm_w + l*DIN, xnf);
            gemm_f16x2_kernel<<<dim3(ROWS/128, 2*DM/128), 256>>>(
                xnf, wih + (size_t)l*2*DM*KW_IN, wil + (size_t)l*2*DM*KW_IN,
                ab, ROWS, 2*DM, DIN, nullptr, nullptr, 0);
        }
        conv_silu_kernel<<<dim3(DM/256, ROWS), 256>>>(cw + l*DM*4, cb + l*DM);
        small_proj_kernel<<<ROWS/16, 256>>>(wpack + (size_t)l*128*DM);
        // delta = softplus(dt @ sD1w^T + sD1b)   (2048 x 1536, K=96)  [fp16 2-pass]
        gemm_f16x2_kernel<<<dim3(ROWS/128, DM/128), 256>>>(
            dtf, d1h + (size_t)l*DM*KW_DD, d1l + (size_t)l*DM*KW_DD,
            delta, ROWS, DM, DD, sD1b + l*DM, nullptr, 1);
        scan_kernel<<<dim3(DM/8, BB), 128>>>(A_log + (size_t)l*DM*DS, Dp + l*DM);
        // seq = sout @ out_proj^T + seq   (2048 x 768, K=1536)  [fp16 2-pass]
        gemm_f16x2_kernel<<<dim3(ROWS/128, DIN/128), 256>>>(
            sof, woh + (size_t)l*DIN*KW_DM, wol + (size_t)l*DIN*KW_DM,
            seq, ROWS, DIN, DM, nullptr, seq, 0);
    }

    rmsnorm_kernel<<<ROWS, 256>>>(seq, norm_f, xnf);
    // logits = xn @ head_w^T   (2048 x 32000, K=768)  [fp16 single pass]
    gemm_fp16_kernel<<<dim3(ROWS/128, VOCAB/128), 256>>>(
        xnf, whf, out, ROWS, VOCAB, DIN);
}

// round 15
// speedup vs baseline: 1.0102x; 1.0069x over previous
#include <cuda_runtime.h>
#include <cuda_bf16.h>
#include <cuda_fp16.h>
#include <cstdint>

#define BB 2
#define LL 1024
#define DIN 768
#define DM 1536
#define DS 16
#define DD 96
#define NL 4
#define ROWS (BB*LL)   // 2048
#define VOCAB 32000
#define KW_IN (DIN/2)  // 384
#define KW_DM (DM/2)   // 768
#define KW_DD (DD/2)   // 48

// ---------------- scratch (static device globals; no allocation) ----------------
__device__ float g_seq[ROWS*DIN];
__device__ float g_ab [ROWS*2*DM];
__device__ float g_ac [ROWS*DM];
__device__ float g_Bm [ROWS*DS];
__device__ float g_Cm [ROWS*DS];
__device__ float g_delta[ROWS*DM];
__device__ float g_wpack[NL*128*DM];

// packed fp16x2 activations (single array each — weights carry the split)
__device__ unsigned g_xn_fp[ROWS*KW_IN];
__device__ unsigned g_so_fp[ROWS*KW_DM];
__device__ unsigned g_dt_fp[ROWS*KW_DD];
// weights: exact fp16 hi/lo split (hi+lo == fp32 weight to ~22 bits)
__device__ unsigned g_wi_hi[NL*2*DM*KW_IN], g_wi_lo[NL*2*DM*KW_IN];
__device__ unsigned g_wo_hi[NL*DIN*KW_DM],  g_wo_lo[NL*DIN*KW_DM];
__device__ unsigned g_d1_hi[NL*DM*KW_DD],   g_d1_lo[NL*DM*KW_DD];
// head weights single fp16 (1-pass head)
__device__ unsigned g_wh_fp[VOCAB*KW_IN];

__device__ __forceinline__ float siluf(float x){ return x / (1.f + __expf(-x)); }
__device__ __forceinline__ float softplusf(float x){ return fmaxf(x,0.f) + log1pf(expf(-fabsf(x))); }

__device__ __forceinline__ unsigned pack_fp16(float x0, float x1){
    __half h0 = __float2half_rn(x0);
    __half h1 = __float2half_rn(x1);
    return ((unsigned)__half_as_ushort(h1) << 16) | __half_as_ushort(h0);
}
__device__ __forceinline__ unsigned pack_fp16_split(float x0, float x1, unsigned &lopair){
    __half h0 = __float2half_rn(x0);
    __half h1 = __float2half_rn(x1);
    __half l0 = __float2half_rn(x0 - __half2float(h0));
    __half l1 = __float2half_rn(x1 - __half2float(h1));
    lopair = ((unsigned)__half_as_ushort(l1) << 16) | __half_as_ushort(l0);
    return ((unsigned)__half_as_ushort(h1) << 16) | __half_as_ushort(h0);
}

__device__ __forceinline__ void mma_fp16(float* d, const unsigned* a, const unsigned* b){
    asm volatile(
      "mma.sync.aligned.m16n8k16.row.col.f32.f16.f16.f32 "
      "{%0,%1,%2,%3}, {%4,%5,%6,%7}, {%8,%9}, {%0,%1,%2,%3};\n"
      : "+f"(d[0]),"+f"(d[1]),"+f"(d[2]),"+f"(d[3])
      : "r"(a[0]),"r"(a[1]),"r"(a[2]),"r"(a[3]), "r"(b[0]),"r"(b[1]));
}
__device__ __forceinline__ void cp16(unsigned smaddr, const void* g){
    asm volatile("cp.async.cg.shared.global [%0], [%1], 16;" :: "r"(smaddr), "l"(g));
}
__device__ __forceinline__ void ldsm4(unsigned &r0, unsigned &r1, unsigned &r2, unsigned &r3,
                                      unsigned addr){
    asm volatile("ldmatrix.sync.aligned.m8n8.x4.shared.b16 {%0,%1,%2,%3}, [%4];"
      : "=r"(r0),"=r"(r1),"=r"(r2),"=r"(r3) : "r"(addr));
}

// ---------------- weight split: fp32 [Nrows,K] -> packed fp16x2 hi/lo (exact) --------
__global__ void split16_kernel(const float* __restrict__ src, unsigned* __restrict__ hi,
                               unsigned* __restrict__ lo, int totalWords, int K){
    int idx = blockIdx.x*256 + threadIdx.x;
    if (idx >= totalWords) return;
    int Kw = K >> 1;
    int n = idx / Kw, w = idx - n*Kw;
    int k = 2*w;
    unsigned l; unsigned h = pack_fp16_split(src[(size_t)n*K + k], src[(size_t)n*K + k + 1], l);
    hi[idx] = h; lo[idx] = l;
}

// ---------------- fp16 pack: fp32 [Nrows,K] -> packed fp16x2 ----------------
__global__ void fp16_pack_kernel(const float* __restrict__ src, unsigned* __restrict__ dst,
                                 int totalWords, int K){
    int idx = blockIdx.x*256 + threadIdx.x;
    if (idx >= totalWords) return;
    int Kw = K >> 1;
    int n = idx / Kw, w = idx - n*Kw;
    int k = 2*w;
    dst[idx] = pack_fp16(src[(size_t)n*K + k], src[(size_t)n*K + k + 1]);
}

// ---------------- embedding gather ----------------
__global__ void embed_kernel(const int* __restrict__ tok, const float* __restrict__ emb){
    int row = blockIdx.x;
    int t = tok[row];
    for (int c = threadIdx.x; c < DIN; c += blockDim.x)
        g_seq[row*DIN + c] = emb[t*DIN + c];
}

// ---------------- rmsnorm -> packed fp16 output ----------------
__global__ void rmsnorm_kernel(const float* __restrict__ in, const float* __restrict__ w,
                               unsigned* __restrict__ fp){
    int row = blockIdx.x;
    float ss = 0.f;
    #pragma unroll
    for (int i = 0; i < 3; i++){
        float x = in[row*DIN + threadIdx.x + i*256];
        ss += x*x;
    }
    #pragma unroll
    for (int off = 16; off > 0; off >>= 1) ss += __shfl_xor_sync(0xffffffffu, ss, off);
    __shared__ float red[8];
    if ((threadIdx.x & 31) == 0) red[threadIdx.x >> 5] = ss;
    __syncthreads();
    float ms = 0.f;
    #pragma unroll
    for (int i = 0; i < 8; i++) ms += red[i];
    float r = rsqrtf(ms * (1.f/768.f) + 1e-6f);
    for (int p = threadIdx.x; p < KW_IN; p += 256){
        int c = 2*p;
        float y0 = in[row*DIN + c]     * r * w[c];
        float y1 = in[row*DIN + c + 1] * r * w[c+1];
        fp[row*KW_IN + p] = pack_fp16(y0, y1);
    }
}

// ========== 2-pass fp16 GEMM (128x128 tile), ldmatrix, 1 barrier/iter ==========
#define RW 12                       // words per row (48B: conflict-free LDSM phases)
#define ARW (128*RW)                // words per 128-row operand array
#define STW3 (3*ARW)                // words per stage (A,Bhi,Blo)
__global__ void __launch_bounds__(256,2) gemm_f16x2_kernel(
    const unsigned* __restrict__ A,
    const unsigned* __restrict__ Bhi, const unsigned* __restrict__ Blo,
    float* __restrict__ C, int M, int N, int K,
    const float* __restrict__ bias, const float* __restrict__ resid, int act)
{
    __shared__ unsigned sm[2*STW3];
    unsigned smb = (unsigned)__cvta_generic_to_shared(sm);
    int tid = threadIdx.x;
    int lane = tid & 31, warp = tid >> 5;
    int qr = lane >> 2, q = lane & 3;
    int m0 = (warp >> 1) * 32, n0 = (warp & 1) * 64;
    int brow = blockIdx.x * 128, bcol = blockIdx.y * 128;
    int Kw = K >> 1;
    int lrow = tid >> 1;
    unsigned sidx = (unsigned)(lrow*RW + (tid & 1)*4);

    const unsigned* gA  = A   + (size_t)(brow + lrow)*Kw + (tid & 1)*4;
    const unsigned* gBh = Bhi + (size_t)(bcol + lrow)*Kw + (tid & 1)*4;
    const unsigned* gBl = Blo + (size_t)(bcol + lrow)*Kw + (tid & 1)*4;

    unsigned aOff[2], bhOff[4], blOff[4];
    #pragma unroll
    for (int im = 0; im < 2; im++)
        aOff[im] = (unsigned)((m0 + im*16 + (lane & 15))*RW + (lane >> 4)*4);
    #pragma unroll
    for (int jp = 0; jp < 4; jp++){
        int rowB = n0 + (2*jp + (lane >> 4))*8 + (lane & 7);
        unsigned off = (unsigned)(rowB*RW + ((lane >> 3) & 1)*4);
        bhOff[jp] = ARW   + off;
        blOff[jp] = 2*ARW + off;
    }

    float acc[2][8][4];
    #pragma unroll
    for (int im = 0; im < 2; im++)
        #pragma unroll
        for (int jn = 0; jn < 8; jn++)
            #pragma unroll
            for (int e = 0; e < 4; e++) acc[im][jn][e] = 0.f;

    int kt = K >> 4;

    cp16(smb + sidx*4,           gA);
    cp16(smb + (ARW + sidx)*4,   gBh);
    cp16(smb + (2*ARW + sidx)*4, gBl);
    asm volatile("cp.async.commit_group;");

    for (int k = 0; k < kt; k++){
        asm volatile("cp.async.wait_group 0;");
        __syncthreads();
        if (k + 1 < kt){
            unsigned s2 = ((k+1) & 1) ? (unsigned)STW3*4 : 0u;
            size_t off = (size_t)(k+1) * 8;
            cp16(smb + s2 + sidx*4,           gA  + off);
            cp16(smb + s2 + (ARW + sidx)*4,   gBh + off);
            cp16(smb + s2 + (2*ARW + sidx)*4, gBl + off);
            asm volatile("cp.async.commit_group;");
        }
        unsigned stB = (k & 1) ? (unsigned)STW3*4 : 0u;

        unsigned a[2][4];
        ldsm4(a[0][0], a[0][1], a[0][2], a[0][3], smb + stB + aOff[0]*4);
        ldsm4(a[1][0], a[1][1], a[1][2], a[1][3], smb + stB + aOff[1]*4);
        #pragma unroll
        for (int jp = 0; jp < 4; jp++){
            unsigned bh[4], bl[4];
            ldsm4(bh[0], bh[1], bh[2], bh[3], smb + stB + bhOff[jp]*4);
            ldsm4(bl[0], bl[1], bl[2], bl[3], smb + stB + blOff[jp]*4);
            #pragma unroll
            for (int im = 0; im < 2; im++) mma_fp16(acc[im][2*jp],   a[im], bh + 0);
            #pragma unroll
            for (int im = 0; im < 2; im++) mma_fp16(acc[im][2*jp],   a[im], bl + 0);
            #pragma unroll
            for (int im = 0; im < 2; im++) mma_fp16(acc[im][2*jp+1], a[im], bh + 2);
            #pragma unroll
            for (int im = 0; im < 2; im++) mma_fp16(acc[im][2*jp+1], a[im], bl + 2);
        }
    }

    #pragma unroll
    for (int im = 0; im < 2; im++){
        #pragma unroll
        for (int h = 0; h < 2; h++){
            int m = brow + m0 + im*16 + qr + h*8;
            #pragma unroll
            for (int jn = 0; jn < 8; jn++){
                int n = bcol + n0 + jn*8 + 2*q;
                float v0 = acc[im][jn][h*2 + 0];
                float v1 = acc[im][jn][h*2 + 1];
                if (bias){ v0 += bias[n]; v1 += bias[n+1]; }
                if (act){ v0 = softplusf(v0); v1 = softplusf(v1); }
                if (resid){ v0 += resid[(size_t)m*N + n]; v1 += resid[(size_t)m*N + n + 1]; }
                *(float2*)&C[(size_t)m*N + n] = make_float2(v0, v1);
            }
        }
    }
}

// ========== 2-pass fp16 GEMM, 64x128 CTA tile (for small-grid GEMMs) ==========
// 8 warps as 2M x 4N, warp tile 32x32. Same accumulation order -> bit-identical.
#define ARW64 (64*RW)               // A: 64 rows
#define BRW   (128*RW)              // B: 128 rows
#define STW64 (ARW64 + 2*BRW)       // stage words
__global__ void __launch_bounds__(256,2) gemm_f16x2_m64_kernel(
    const unsigned* __restrict__ A,
    const unsigned* __restrict__ Bhi, const unsigned* __restrict__ Blo,
    float* __restrict__ C, int M, int N, int K,
    const float* __restrict__ bias, const float* __restrict__ resid, int act)
{
    __shared__ unsigned sm[2*STW64];
    unsigned smb = (unsigned)__cvta_generic_to_shared(sm);
    int tid = threadIdx.x;
    int lane = tid & 31, warp = tid >> 5;
    int qr = lane >> 2, q = lane & 3;
    int m0 = (warp & 1) * 32, n0 = (warp >> 1) * 32;
    int brow = blockIdx.x * 64, bcol = blockIdx.y * 128;
    int Kw = K >> 1;
    int lrow = tid >> 1;
    unsigned sidxB = (unsigned)(lrow*RW + (tid & 1)*4);

    const unsigned* gA  = A   + (size_t)(brow + (lrow & 63))*Kw + (tid & 1)*4;
    const unsigned* gBh = Bhi + (size_t)(bcol + lrow)*Kw + (tid & 1)*4;
    const unsigned* gBl = Blo + (size_t)(bcol + lrow)*Kw + (tid & 1)*4;

    unsigned aOff[2], bhOff[2], blOff[2];
    #pragma unroll
    for (int im = 0; im < 2; im++)
        aOff[im] = (unsigned)((m0 + im*16 + (lane & 15))*RW + (lane >> 4)*4);
    #pragma unroll
    for (int jp = 0; jp < 2; jp++){
        int rowB = n0 + (2*jp + (lane >> 4))*8 + (lane & 7);
        unsigned off = (unsigned)(rowB*RW + ((lane >> 3) & 1)*4);
        bhOff[jp] = ARW64       + off;
        blOff[jp] = ARW64 + BRW + off;
    }

    float acc[2][4][4];
    #pragma unroll
    for (int im = 0; im < 2; im++)
        #pragma unroll
        for (int jn = 0; jn < 4; jn++)
            #pragma unroll
            for (int e = 0; e < 4; e++) acc[im][jn][e] = 0.f;

    int kt = K >> 4;

    if (tid < 128) cp16(smb + sidxB*4, gA);
    cp16(smb + (ARW64 + sidxB)*4,       gBh);
    cp16(smb + (ARW64 + BRW + sidxB)*4, gBl);
    asm volatile("cp.async.commit_group;");

    for (int k = 0; k < kt; k++){
        asm volatile("cp.async.wait_group 0;");
        __syncthreads();
        if (k + 1 < kt){
            unsigned s2 = ((k+1) & 1) ? (unsigned)STW64*4 : 0u;
            size_t off = (size_t)(k+1) * 8;
            if (tid < 128) cp16(smb + s2 + sidxB*4, gA + off);
            cp16(smb + s2 + (ARW64 + sidxB)*4,       gBh + off);
            cp16(smb + s2 + (ARW64 + BRW + sidxB)*4, gBl + off);
            asm volatile("cp.async.commit_group;");
        }
        unsigned stB = (k & 1) ? (unsigned)STW64*4 : 0u;

        unsigned a[2][4];
        ldsm4(a[0][0], a[0][1], a[0][2], a[0][3], smb + stB + aOff[0]*4);
        ldsm4(a[1][0], a[1][1], a[1][2], a[1][3], smb + stB + aOff[1]*4);
        #pragma unroll
        for (int jp = 0; jp < 2; jp++){
            unsigned bh[4], bl[4];
            ldsm4(bh[0], bh[1], bh[2], bh[3], smb + stB + bhOff[jp]*4);
            ldsm4(bl[0], bl[1], bl[2], bl[3], smb + stB + blOff[jp]*4);
            #pragma unroll
            for (int im = 0; im < 2; im++) mma_fp16(acc[im][2*jp],   a[im], bh + 0);
            #pragma unroll
            for (int im = 0; im < 2; im++) mma_fp16(acc[im][2*jp],   a[im], bl + 0);
            #pragma unroll
            for (int im = 0; im < 2; im++) mma_fp16(acc[im][2*jp+1], a[im], bh + 2);
            #pragma unroll
            for (int im = 0; im < 2; im++) mma_fp16(acc[im][2*jp+1], a[im], bl + 2);
        }
    }

    #pragma unroll
    for (int im = 0; im < 2; im++){
        #pragma unroll
        for (int h = 0; h < 2; h++){
            int m = brow + m0 + im*16 + qr + h*8;
            #pragma unroll
            for (int jn = 0; jn < 4; jn++){
                int n = bcol + n0 + jn*8 + 2*q;
                float v0 = acc[im][jn][h*2 + 0];
                float v1 = acc[im][jn][h*2 + 1];
                if (bias){ v0 += bias[n]; v1 += bias[n+1]; }
                if (act){ v0 = softplusf(v0); v1 = softplusf(v1); }
                if (resid){ v0 += resid[(size_t)m*N + n]; v1 += resid[(size_t)m*N + n + 1]; }
                *(float2*)&C[(size_t)m*N + n] = make_float2(v0, v1);
            }
        }
    }
}

// ========== single-pass fp16 GEMM (head), ldmatrix, 1 barrier/iter ==========
#define STW2 (2*ARW)
__global__ void __launch_bounds__(256,2) gemm_fp16_kernel(
    const unsigned* __restrict__ A, const unsigned* __restrict__ B,
    float* __restrict__ C, int M, int N, int K)
{
    __shared__ unsigned sm[2*STW2];
    unsigned smb = (unsigned)__cvta_generic_to_shared(sm);
    int tid = threadIdx.x;
    int lane = tid & 31, warp = tid >> 5;
    int qr = lane >> 2, q = lane & 3;
    int m0 = (warp >> 1) * 32, n0 = (warp & 1) * 64;
    int brow = blockIdx.x * 128, bcol = blockIdx.y * 128;
    int Kw = K >> 1;
    int lrow = tid >> 1;
    unsigned sidx = (unsigned)(lrow*RW + (tid & 1)*4);

    const unsigned* gA = A + (size_t)(brow + lrow)*Kw + (tid & 1)*4;
    const unsigned* gB = B + (size_t)(bcol + lrow)*Kw + (tid & 1)*4;

    unsigned aOff[2], bOff[4];
    #pragma unroll
    for (int im = 0; im < 2; im++)
        aOff[im] = (unsigned)((m0 + im*16 + (lane & 15))*RW + (lane >> 4)*4);
    #pragma unroll
    for (int jp = 0; jp < 4; jp++){
        int rowB = n0 + (2*jp + (lane >> 4))*8 + (lane & 7);
        bOff[jp] = (unsigned)(ARW + rowB*RW + ((lane >> 3) & 1)*4);
    }

    float acc[2][8][4];
    #pragma unroll
    for (int im = 0; im < 2; im++)
        #pragma unroll
        for (int jn = 0; jn < 8; jn++)
            #pragma unroll
            for (int e = 0; e < 4; e++) acc[im][jn][e] = 0.f;

    int kt = K >> 4;

    cp16(smb + sidx*4,         gA);
    cp16(smb + (ARW + sidx)*4, gB);
    asm volatile("cp.async.commit_group;");

    for (int k = 0; k < kt; k++){
        asm volatile("cp.async.wait_group 0;");
        __syncthreads();
        if (k + 1 < kt){
            unsigned s2 = ((k+1) & 1) ? (unsigned)STW2*4 : 0u;
            size_t off = (size_t)(k+1) * 8;
            cp16(smb + s2 + sidx*4,         gA + off);
            cp16(smb + s2 + (ARW + sidx)*4, gB + off);
            asm volatile("cp.async.commit_group;");
        }
        unsigned stB = (k & 1) ? (unsigned)STW2*4 : 0u;

        unsigned a[2][4];
        ldsm4(a[0][0], a[0][1], a[0][2], a[0][3], smb + stB + aOff[0]*4);
        ldsm4(a[1][0], a[1][1], a[1][2], a[1][3], smb + stB + aOff[1]*4);
        #pragma unroll
        for (int jp = 0; jp < 4; jp++){
            unsigned b[4];
            ldsm4(b[0], b[1], b[2], b[3], smb + stB + bOff[jp]*4);
            #pragma unroll
            for (int im = 0; im < 2; im++) mma_fp16(acc[im][2*jp],   a[im], b + 0);
            #pragma unroll
            for (int im = 0; im < 2; im++) mma_fp16(acc[im][2*jp+1], a[im], b + 2);
        }
    }

    #pragma unroll
    for (int im = 0; im < 2; im++){
        #pragma unroll
        for (int h = 0; h < 2; h++){
            int m = brow + m0 + im*16 + qr + h*8;
            #pragma unroll
            for (int jn = 0; jn < 8; jn++){
                int n = bcol + n0 + jn*8 + 2*q;
                *(float2*)&C[(size_t)m*N + n] =
                    make_float2(acc[im][jn][h*2 + 0], acc[im][jn][h*2 + 1]);
            }
        }
    }
}

// ---------------- causal depthwise conv (K=4) + SiLU ----------------
__global__ void conv_silu_kernel(const float* __restrict__ cw, const float* __restrict__ cb){
    int d = blockIdx.x * blockDim.x + threadIdx.x;
    int row = blockIdx.y;
    int t = row & (LL-1);
    float4 w = *(const float4*)(cw + d*4);
    float acc = cb[d];
    const float* p = g_ab + (size_t)row*(2*DM) + d;
    if (t >= 3) acc += p[-3*2*DM]*w.x;
    if (t >= 2) acc += p[-2*2*DM]*w.y;
    if (t >= 1) acc += p[-1*2*DM]*w.z;
    acc += p[0]*w.w;
    g_ac[(size_t)row*DM + d] = siluf(acc);
}

// ---------------- pack sB|sC|sD0 into one [NL][128][DM] weight ----------------
__global__ void pack_kernel(const float* __restrict__ sB, const float* __restrict__ sC,
                            const float* __restrict__ sD0){
    int idx = blockIdx.x*256 + threadIdx.x;
    if (idx >= NL*128*DM) return;
    int k = idx % DM;
    int n = (idx / DM) & 127;
    int l = idx / (128*DM);
    float v;
    if (n < 16)      v = sB [((size_t)l*DS + n     )*DM + k];
    else if (n < 32) v = sC [((size_t)l*DS + (n-16))*DM + k];
    else             v = sD0[((size_t)l*DD + (n-32))*DM + k];
    g_wpack[idx] = v;
}

// ---------------- fused small projections: [16 rows] x [128 outs], K=1536 ----------------
#define SP_KC 64
__global__ void __launch_bounds__(256) small_proj_kernel(const float* __restrict__ wp){
    __shared__ float Ws[128][SP_KC+1];
    __shared__ float Xs[16][SP_KC+4];
    int m0  = blockIdx.x * 16;
    int tid = threadIdx.x;
    int n2  = tid & 63;
    int mh  = tid >> 6;
    float acc[2][4] = {{0.f,0.f,0.f,0.f},{0.f,0.f,0.f,0.f}};

    for (int k0 = 0; k0 < DM; k0 += SP_KC){
        #pragma unroll
        for (int j = 0; j < 8; j++){
            int idx = tid + j*256;
            int r = idx >> 4, c4 = (idx & 15) << 2;
            float4 v = *(const float4*)(wp + (size_t)r*DM + k0 + c4);
            Ws[r][c4+0]=v.x; Ws[r][c4+1]=v.y; Ws[r][c4+2]=v.z; Ws[r][c4+3]=v.w;
        }
        {
            int r = tid >> 4, c4 = (tid & 15) << 2;
            float4 v = *(const float4*)(g_ac + (size_t)(m0+r)*DM + k0 + c4);
            Xs[r][c4+0]=v.x; Xs[r][c4+1]=v.y; Xs[r][c4+2]=v.z; Xs[r][c4+3]=v.w;
        }
        __syncthreads();
        #pragma unroll 8
        for (int kk = 0; kk < SP_KC; kk++){
            float w0 = Ws[2*n2][kk], w1 = Ws[2*n2+1][kk];
            #pragma unroll
            for (int i = 0; i < 4; i++){
                float x = Xs[mh*4+i][kk];
                acc[0][i] += w0*x;
                acc[1][i] += w1*x;
            }
        }
        __syncthreads();
    }
    #pragma unroll
    for (int i = 0; i < 4; i++){
        int m = m0 + mh*4 + i;
        int n = 2*n2;
        if (n2 < 8){
            g_Bm[m*DS + n]   = acc[0][i];
            g_Bm[m*DS + n+1] = acc[1][i];
        } else if (n2 < 16){
            g_Cm[m*DS + (n-16)]   = acc[0][i];
            g_Cm[m*DS + (n-16)+1] = acc[1][i];
        } else {
            g_dt_fp[m*KW_DD + (n2-16)] = pack_fp16(acc[0][i], acc[1][i]);
        }
    }
}

// ---------------- selective scan, prefetch ring depth 8; fp16 packed out -----------
#define PD 8
__global__ void scan_kernel(const float* __restrict__ A_log, const float* __restrict__ Dp){
    int lane = threadIdx.x & 31, warp = threadIdx.x >> 5;
    int s = lane & 15;
    int d = blockIdx.x*8 + warp*2 + (lane >> 4);
    int b = blockIdx.y;
    float Acoef = -expf(A_log[d*DS + s]);
    float Dv = Dp[d];
    const float* pd = g_delta + (size_t)(b*LL)*DM + d;
    const float* pa = g_ac    + (size_t)(b*LL)*DM + d;
    const float* pg = g_ab    + (size_t)(b*LL)*(2*DM) + DM + d;
    const float* pB = g_Bm    + (size_t)(b*LL)*DS + s;
    const float* pC = g_Cm    + (size_t)(b*LL)*DS + s;
    float f_d[PD], f_a[PD], f_g[PD], f_B[PD], f_C[PD];
    #pragma unroll
    for (int i = 0; i < PD; i++){
        f_d[i] = pd[(size_t)i*DM];
        f_a[i] = pa[(size_t)i*DM];
        f_g[i] = pg[(size_t)i*2*DM];
        f_B[i] = pB[(size_t)i*DS];
        f_C[i] = pC[(size_t)i*DS];
    }
    float h = 0.f;
    int p = blockIdx.x*4 + warp;        // d-pair index within KW_DM
    int wbase = (b*LL)*KW_DM + p;
    #pragma unroll 8
    for (int t = 0; t < LL; t++){
        int sl = t & (PD-1);
        float dc = f_d[sl], a_c = f_a[sl], gc = f_g[sl];
        float bc = f_B[sl], cc = f_C[sl];
        int tn = t + PD;
        if (tn < LL){
            f_d[sl] = pd[(size_t)tn*DM];
            f_a[sl] = pa[(size_t)tn*DM];
            f_g[sl] = pg[(size_t)tn*2*DM];
            f_B[sl] = pB[(size_t)tn*DS];
            f_C[sl] = pC[(size_t)tn*DS];
        }
        h = __expf(dc*Acoef)*h + dc*bc*a_c;
        float c = h*cc;
        c += __shfl_xor_sync(0xffffffffu, c, 8);
        c += __shfl_xor_sync(0xffffffffu, c, 4);
        c += __shfl_xor_sync(0xffffffffu, c, 2);
        c += __shfl_xor_sync(0xffffffffu, c, 1);
        float o = (c + Dv*a_c) * siluf(gc);
        float o2 = __shfl_xor_sync(0xffffffffu, o, 16);
        if (lane == 0)
            g_so_fp[wbase + t*KW_DM] = pack_fp16(o, o2);
    }
}

// ---------------- launch ----------------
extern "C" void kernel_launch(void* const* d_in, const int* in_sizes, int n_in,
                              void* d_out, int out_size)
{
    const int*   tok      = (const int*)  d_in[0];
    const float* emb      = (const float*)d_in[1];
    const float* in_proj  = (const float*)d_in[2];
    const float* out_proj = (const float*)d_in[3];
    const float* sB       = (const float*)d_in[4];
    const float* sC       = (const float*)d_in[5];
    const float* sD0      = (const float*)d_in[6];
    const float* sD1w     = (const float*)d_in[7];
    const float* sD1b     = (const float*)d_in[8];
    const float* cw       = (const float*)d_in[9];
    const float* cb       = (const float*)d_in[10];
    const float* A_log    = (const float*)d_in[11];
    const float* Dp       = (const float*)d_in[12];
    const float* norm_w   = (const float*)d_in[13];
    const float* norm_f   = (const float*)d_in[14];
    const float* head_w   = (const float*)d_in[15];
    float* out = (float*)d_out;

    float *seq,*ab,*delta,*wpack;
    unsigned *xnf,*sof,*dtf,*wih,*wil,*woh,*wol,*d1h,*d1l,*whf;
    cudaGetSymbolAddress((void**)&seq,   g_seq);
    cudaGetSymbolAddress((void**)&ab,    g_ab);
    cudaGetSymbolAddress((void**)&delta, g_delta);
    cudaGetSymbolAddress((void**)&wpack, g_wpack);
    cudaGetSymbolAddress((void**)&xnf, g_xn_fp);
    cudaGetSymbolAddress((void**)&sof, g_so_fp);
    cudaGetSymbolAddress((void**)&dtf, g_dt_fp);
    cudaGetSymbolAddress((void**)&wih, g_wi_hi); cudaGetSymbolAddress((void**)&wil, g_wi_lo);
    cudaGetSymbolAddress((void**)&woh, g_wo_hi); cudaGetSymbolAddress((void**)&wol, g_wo_lo);
    cudaGetSymbolAddress((void**)&d1h, g_d1_hi); cudaGetSymbolAddress((void**)&d1l, g_d1_lo);
    cudaGetSymbolAddress((void**)&whf, g_wh_fp);

    // order chosen so launch #3 is the in_proj GEMM (ncu capture slot)
    embed_kernel<<<ROWS, 256>>>(tok, emb);                                            // 0
    split16_kernel<<<(NL*2*DM*KW_IN + 255)/256, 256>>>(in_proj, wih, wil,
                                                       NL*2*DM*KW_IN, DIN);           // 1
    rmsnorm_kernel<<<ROWS, 256>>>(seq, norm_w, xnf);                                  // 2
    gemm_f16x2_kernel<<<dim3(ROWS/128, 2*DM/128), 256>>>(
        xnf, wih, wil, ab, ROWS, 2*DM, DIN, nullptr, nullptr, 0);                     // 3
    pack_kernel<<<(NL*128*DM + 255)/256, 256>>>(sB, sC, sD0);                         // 4
    split16_kernel<<<(NL*DIN*KW_DM + 255)/256, 256>>>(out_proj, woh, wol,
                                                      NL*DIN*KW_DM, DM);              // 5
    split16_kernel<<<(NL*DM*KW_DD + 255)/256, 256>>>(sD1w, d1h, d1l,
                                                     NL*DM*KW_DD, DD);                // 6
    fp16_pack_kernel<<<(VOCAB*KW_IN + 255)/256, 256>>>(head_w, whf, VOCAB*KW_IN, DIN);// 7

    for (int l = 0; l < NL; l++){
        if (l > 0){
            rmsnorm_kernel<<<ROWS, 256>>>(seq, norm_w + l*DIN, xnf);
            gemm_f16x2_kernel<<<dim3(ROWS/128, 2*DM/128), 256>>>(
                xnf, wih + (size_t)l*2*DM*KW_IN, wil + (size_t)l*2*DM*KW_IN,
                ab, ROWS, 2*DM, DIN, nullptr, nullptr, 0);
        }
        conv_silu_kernel<<<dim3(DM/256, ROWS), 256>>>(cw + l*DM*4, cb + l*DM);
        small_proj_kernel<<<ROWS/16, 256>>>(wpack + (size_t)l*128*DM);
        // delta = softplus(dt @ sD1w^T + sD1b)   (2048 x 1536, K=96)  [M64 tile]
        gemm_f16x2_m64_kernel<<<dim3(ROWS/64, DM/128), 256>>>(
            dtf, d1h + (size_t)l*DM*KW_DD, d1l + (size_t)l*DM*KW_DD,
            delta, ROWS, DM, DD, sD1b + l*DM, nullptr, 1);
        scan_kernel<<<dim3(DM/8, BB), 128>>>(A_log + (size_t)l*DM*DS, Dp + l*DM);
        // seq = sout @ out_proj^T + seq   (2048 x 768, K=1536)  [M64 tile]
        gemm_f16x2_m64_kernel<<<dim3(ROWS/64, DIN/128), 256>>>(
            sof, woh + (size_t)l*DIN*KW_DM, wol + (size_t)l*DIN*KW_DM,
            seq, ROWS, DIN, DM, nullptr, seq, 0);
    }

    rmsnorm_kernel<<<ROWS, 256>>>(seq, norm_f, xnf);
    // logits = xn @ head_w^T   (2048 x 32000, K=768)  [fp16 single pass]
    gemm_fp16_kernel<<<dim3(ROWS/128, VOCAB/128), 256>>>(
        xnf, whf, out, ROWS, VOCAB, DIN);
}